// round 11
// baseline (speedup 1.0000x reference)
#include <cuda_runtime.h>
#include <cuda_bf16.h>
#include <cstdint>
#include <cmath>

#define NMAX 100000
#define EMAX 1600000
#define FDIM 128

// ---------------------------------------------------------------------------
// device globals (allocation-free scratch)
// ---------------------------------------------------------------------------
__device__ int   g_is64;
__device__ int   g_cnt[NMAX];
__device__ int   g_off[NMAX + 1];
__device__ int   g_cur[NMAX];
__device__ int   g_eidx[EMAX];
__device__ float g_dinv[NMAX];
__device__ float g_y[(size_t)NMAX * FDIM];
__device__ float g_agg[(size_t)NMAX * FDIM];
// pre-split W as bf16 pairs, plain [k][n/2] uint32 layout (128 x 64), 2 slots
__device__ __align__(16) uint32_t g_Whi[2][8192];
__device__ __align__(16) uint32_t g_Wlo[2][8192];

// ---------------------------------------------------------------------------
// warp-level MMA helpers (sm_80+ ISA: safe for plain sm_103 target)
// ---------------------------------------------------------------------------
__device__ __forceinline__ uint32_t smem_to_u32(const void* p) {
    uint32_t a;
    asm("{ .reg .u64 t; cvta.to.shared.u64 t, %1; cvt.u32.u64 %0, t; }"
        : "=r"(a) : "l"(p));
    return a;
}

#define LDSM_X4(r0, r1, r2, r3, addr) \
    asm volatile("ldmatrix.sync.aligned.m8n8.x4.shared.b16 {%0,%1,%2,%3}, [%4];" \
                 : "=r"(r0), "=r"(r1), "=r"(r2), "=r"(r3) : "r"(addr))
#define LDSM_X4_T(r0, r1, r2, r3, addr) \
    asm volatile("ldmatrix.sync.aligned.m8n8.x4.trans.shared.b16 {%0,%1,%2,%3}, [%4];" \
                 : "=r"(r0), "=r"(r1), "=r"(r2), "=r"(r3) : "r"(addr))

__device__ __forceinline__ void mma16816(float* c, const uint32_t* a,
                                         const uint32_t* b) {
    asm volatile(
        "mma.sync.aligned.m16n8k16.row.col.f32.bf16.bf16.f32 "
        "{%0,%1,%2,%3}, {%4,%5,%6,%7}, {%8,%9}, {%0,%1,%2,%3};"
        : "+f"(c[0]), "+f"(c[1]), "+f"(c[2]), "+f"(c[3])
        : "r"(a[0]), "r"(a[1]), "r"(a[2]), "r"(a[3]), "r"(b[0]), "r"(b[1]));
}

// ---------------------------------------------------------------------------
// index dtype detection (+ fused g_cnt zeroing: E >> N so grid covers both)
// ---------------------------------------------------------------------------
__global__ void detect_init_kernel() { g_is64 = 1; }
__global__ void detect_zero_kernel(const unsigned long long* __restrict__ ei,
                                   int E, unsigned long long n64, int n) {
    int i = blockIdx.x * blockDim.x + threadIdx.x;
    if (i < n) g_cnt[i] = 0;
    if (i < E && ei[i] >= n64) g_is64 = 0;
}
__device__ __forceinline__ int load_idx(const void* ei, int i) {
    if (g_is64) return (int)((const long long*)ei)[i];
    return ((const int*)ei)[i];
}

// ---------------------------------------------------------------------------
// CSR build
// ---------------------------------------------------------------------------
__global__ void cnt_accum_kernel(const void* __restrict__ ei, int E, int n) {
    int e = blockIdx.x * blockDim.x + threadIdx.x;
    if (e < E) {
        int d = load_idx(ei, E + e);
        if ((unsigned)d < (unsigned)n) atomicAdd(&g_cnt[d], 1);
    }
}

// single-block scan, 4 elems/thread, shfl warp scans (also computes dinv)
__global__ void __launch_bounds__(1024)
scan_kernel(int n) {
    __shared__ int wsum[32];
    __shared__ int carry_s;
    const int tid = threadIdx.x, lane = tid & 31, w = tid >> 5;
    if (tid == 0) carry_s = 0;
    __syncthreads();
    for (int base = 0; base < n; base += 4096) {
        int i0 = base + tid * 4;
        int v0 = 0, v1 = 0, v2 = 0, v3 = 0;
        if (i0 + 3 < n) {
            int4 v = *reinterpret_cast<const int4*>(g_cnt + i0);
            v0 = v.x; v1 = v.y; v2 = v.z; v3 = v.w;
        } else {
            if (i0 + 0 < n) v0 = g_cnt[i0 + 0];
            if (i0 + 1 < n) v1 = g_cnt[i0 + 1];
            if (i0 + 2 < n) v2 = g_cnt[i0 + 2];
            if (i0 + 3 < n) v3 = g_cnt[i0 + 3];
        }
        if (i0 + 0 < n) g_dinv[i0 + 0] = rsqrtf((float)(v0 + 1));
        if (i0 + 1 < n) g_dinv[i0 + 1] = rsqrtf((float)(v1 + 1));
        if (i0 + 2 < n) g_dinv[i0 + 2] = rsqrtf((float)(v2 + 1));
        if (i0 + 3 < n) g_dinv[i0 + 3] = rsqrtf((float)(v3 + 1));
        int mysum = v0 + v1 + v2 + v3;
        int s = mysum;
#pragma unroll
        for (int off = 1; off < 32; off <<= 1) {
            int t = __shfl_up_sync(0xffffffffu, s, off);
            if (lane >= off) s += t;
        }
        if (lane == 31) wsum[w] = s;
        __syncthreads();
        if (w == 0) {
            int t = wsum[lane];
#pragma unroll
            for (int off = 1; off < 32; off <<= 1) {
                int u = __shfl_up_sync(0xffffffffu, t, off);
                if (lane >= off) t += u;
            }
            wsum[lane] = t;
        }
        __syncthreads();
        int warp_excl = (w > 0) ? wsum[w - 1] : 0;
        int tb = carry_s + warp_excl + (s - mysum);
        if (i0 + 0 < n) { g_off[i0 + 0] = tb; g_cur[i0 + 0] = tb; } tb += v0;
        if (i0 + 1 < n) { g_off[i0 + 1] = tb; g_cur[i0 + 1] = tb; } tb += v1;
        if (i0 + 2 < n) { g_off[i0 + 2] = tb; g_cur[i0 + 2] = tb; } tb += v2;
        if (i0 + 3 < n) { g_off[i0 + 3] = tb; g_cur[i0 + 3] = tb; } tb += v3;
        int total = wsum[31];
        __syncthreads();
        if (tid == 0) carry_s += total;
        __syncthreads();
    }
    if (tid == 0) g_off[n] = carry_s;
}

__global__ void place_kernel(const void* __restrict__ ei, int E, int n) {
    int e = blockIdx.x * blockDim.x + threadIdx.x;
    if (e >= E) return;
    int s = load_idx(ei, e);
    int d = load_idx(ei, E + e);
    if ((unsigned)s >= (unsigned)n || (unsigned)d >= (unsigned)n) return;
    int p = atomicAdd(&g_cur[d], 1);
    g_eidx[p] = s;
}

// ---------------------------------------------------------------------------
// W prep: split W (fp32 [K=128, N=128]) into bf16 hi/lo pairs along n,
// plain [k][n/2] uint32 layout, into slot SLOT.
// ---------------------------------------------------------------------------
template <int SLOT>
__global__ void __launch_bounds__(256)
prep_w_kernel(const float* __restrict__ W) {
    int j = blockIdx.x * blockDim.x + threadIdx.x;  // 0..8191
    if (j >= 8192) return;
    int k = j >> 6;
    int np = (j & 63) * 2;
    float w0 = W[(size_t)k * FDIM + np];
    float w1 = W[(size_t)k * FDIM + np + 1];
    __nv_bfloat16 h0 = __float2bfloat16(w0);
    __nv_bfloat16 h1 = __float2bfloat16(w1);
    __nv_bfloat16 l0 = __float2bfloat16(w0 - __bfloat162float(h0));
    __nv_bfloat16 l1 = __float2bfloat16(w1 - __bfloat162float(h1));
    g_Whi[SLOT][j] = (uint32_t)__bfloat16_as_ushort(h0) |
                     ((uint32_t)__bfloat16_as_ushort(h1) << 16);
    g_Wlo[SLOT][j] = (uint32_t)__bfloat16_as_ushort(l0) |
                     ((uint32_t)__bfloat16_as_ushort(l1) << 16);
}

// ---------------------------------------------------------------------------
// HMMA GEMM: y_row = act(A_row) @ W (NO dinv scaling — deferred to agg).
// fp32 via bf16 3-term split (Ahi*Bhi + Alo*Bhi + Ahi*Blo).
// 128x128 tile/CTA, 8 warps (4x2), K=128.
// LAYER==1: A = X (no dinv/CSR dependency at all!)
// LAYER==2: A = g_agg, act = relu(a*dinv[row] + b1[k]).
// ---------------------------------------------------------------------------
#define SSTRIDE 136   // bf16 elements per smem row (128 + 8 pad)
#define SM_AH 0
#define SM_AL (128 * SSTRIDE)
#define SM_BH (2 * 128 * SSTRIDE)
#define SM_BL (3 * 128 * SSTRIDE)
#define SM_ELEMS (4 * 128 * SSTRIDE)
#define SM_BYTES (SM_ELEMS * 2)

template <int LAYER>
__global__ void __launch_bounds__(256)
gemm_mma_kernel(const float* __restrict__ X,
                const float* __restrict__ bin, int M) {
    extern __shared__ __align__(16) char smem_raw[];
    __nv_bfloat16* sm = reinterpret_cast<__nv_bfloat16*>(smem_raw);
    const uint32_t sbase = smem_to_u32(smem_raw);

    const int tid = threadIdx.x;
    const int wid = tid >> 5;
    const int lane = tid & 31;
    const int warp_m = wid & 3;       // 4 m-strips of 32 rows
    const int warp_n = wid >> 2;      // 2 n-strips of 64 cols
    const int block_row = blockIdx.x * 128;

    const float* Aptr = (LAYER == 1) ? X : (const float*)g_agg;
    const uint32_t* Bhi = g_Whi[LAYER - 1];
    const uint32_t* Blo = g_Wlo[LAYER - 1];

    // --- load A (fp32), activation, split hi/lo into padded smem -----------
#pragma unroll
    for (int i = 0; i < 16; i++) {
        int f4 = tid + i * 256;           // 4096 float4s
        int row = f4 >> 5;
        int c4 = (f4 & 31) * 4;
        int grow = block_row + row;
        float4 av = make_float4(0.f, 0.f, 0.f, 0.f);
        if (grow < M) {
            av = *reinterpret_cast<const float4*>(Aptr + (size_t)grow * FDIM + c4);
            if (LAYER == 2) {
                float dv = g_dinv[grow];
                av.x = fmaxf(fmaf(av.x, dv, bin[c4 + 0]), 0.0f);
                av.y = fmaxf(fmaf(av.y, dv, bin[c4 + 1]), 0.0f);
                av.z = fmaxf(fmaf(av.z, dv, bin[c4 + 2]), 0.0f);
                av.w = fmaxf(fmaf(av.w, dv, bin[c4 + 3]), 0.0f);
            }
        }
        __nv_bfloat16 hx = __float2bfloat16(av.x), hy = __float2bfloat16(av.y);
        __nv_bfloat16 hz = __float2bfloat16(av.z), hw = __float2bfloat16(av.w);
        __nv_bfloat16 lx = __float2bfloat16(av.x - __bfloat162float(hx));
        __nv_bfloat16 ly = __float2bfloat16(av.y - __bfloat162float(hy));
        __nv_bfloat16 lz = __float2bfloat16(av.z - __bfloat162float(hz));
        __nv_bfloat16 lw = __float2bfloat16(av.w - __bfloat162float(hw));
        uint32_t* ah = reinterpret_cast<uint32_t*>(sm + SM_AH + row * SSTRIDE + c4);
        uint32_t* al = reinterpret_cast<uint32_t*>(sm + SM_AL + row * SSTRIDE + c4);
        ah[0] = (uint32_t)__bfloat16_as_ushort(hx) | ((uint32_t)__bfloat16_as_ushort(hy) << 16);
        ah[1] = (uint32_t)__bfloat16_as_ushort(hz) | ((uint32_t)__bfloat16_as_ushort(hw) << 16);
        al[0] = (uint32_t)__bfloat16_as_ushort(lx) | ((uint32_t)__bfloat16_as_ushort(ly) << 16);
        al[1] = (uint32_t)__bfloat16_as_ushort(lz) | ((uint32_t)__bfloat16_as_ushort(lw) << 16);
    }

    // --- copy pre-split B into padded smem (uint4 = 8 bf16) ----------------
#pragma unroll
    for (int i = 0; i < 8; i++) {
        int u = tid + i * 256;            // 2048 uint4 per variant
        int row = u >> 4;
        int c8 = (u & 15) * 8;
        *reinterpret_cast<uint4*>(sm + SM_BH + row * SSTRIDE + c8) =
            *(reinterpret_cast<const uint4*>(Bhi) + u);
        *reinterpret_cast<uint4*>(sm + SM_BL + row * SSTRIDE + c8) =
            *(reinterpret_cast<const uint4*>(Blo) + u);
    }
    __syncthreads();

    // --- main MMA loop ------------------------------------------------------
    float acc[2][8][4];
#pragma unroll
    for (int mt = 0; mt < 2; mt++)
#pragma unroll
        for (int nt = 0; nt < 8; nt++)
#pragma unroll
            for (int q = 0; q < 4; q++) acc[mt][nt][q] = 0.0f;

    const int lrow = lane & 15;
    const int lcol = (lane >> 4) * 8;

#pragma unroll
    for (int ks = 0; ks < 8; ks++) {
        uint32_t ah[2][4], al[2][4], bf[4][4];
#pragma unroll
        for (int mt = 0; mt < 2; mt++) {
            int row = warp_m * 32 + mt * 16 + lrow;
            int col = ks * 16 + lcol;
            uint32_t addr_h = sbase + (uint32_t)((SM_AH + row * SSTRIDE + col) * 2);
            uint32_t addr_l = sbase + (uint32_t)((SM_AL + row * SSTRIDE + col) * 2);
            LDSM_X4(ah[mt][0], ah[mt][1], ah[mt][2], ah[mt][3], addr_h);
            LDSM_X4(al[mt][0], al[mt][1], al[mt][2], al[mt][3], addr_l);
        }
#pragma unroll
        for (int np = 0; np < 4; np++) {
            int r = ks * 16 + lrow;
            int c = warp_n * 64 + np * 16 + lcol;
            uint32_t addr = sbase + (uint32_t)((SM_BH + r * SSTRIDE + c) * 2);
            LDSM_X4_T(bf[np][0], bf[np][1], bf[np][2], bf[np][3], addr);
        }
#pragma unroll
        for (int mt = 0; mt < 2; mt++)
#pragma unroll
            for (int np = 0; np < 4; np++) {
                mma16816(acc[mt][np * 2 + 0], ah[mt], &bf[np][0]);
                mma16816(acc[mt][np * 2 + 1], ah[mt], &bf[np][2]);
                mma16816(acc[mt][np * 2 + 0], al[mt], &bf[np][0]);
                mma16816(acc[mt][np * 2 + 1], al[mt], &bf[np][2]);
            }
#pragma unroll
        for (int np = 0; np < 4; np++) {
            int r = ks * 16 + lrow;
            int c = warp_n * 64 + np * 16 + lcol;
            uint32_t addr = sbase + (uint32_t)((SM_BL + r * SSTRIDE + c) * 2);
            LDSM_X4_T(bf[np][0], bf[np][1], bf[np][2], bf[np][3], addr);
        }
#pragma unroll
        for (int mt = 0; mt < 2; mt++)
#pragma unroll
            for (int np = 0; np < 4; np++) {
                mma16816(acc[mt][np * 2 + 0], ah[mt], &bf[np][0]);
                mma16816(acc[mt][np * 2 + 1], ah[mt], &bf[np][2]);
            }
    }

    // --- epilogue: store raw y (dinv applied later in agg) ------------------
    const int er0 = lane >> 2;            // 0..7
    const int ec = (lane & 3) * 2;
#pragma unroll
    for (int mt = 0; mt < 2; mt++) {
        int row0 = block_row + warp_m * 32 + mt * 16 + er0;
        int row1 = row0 + 8;
#pragma unroll
        for (int nt = 0; nt < 8; nt++) {
            int col = warp_n * 64 + nt * 8 + ec;
            if (row0 < M) {
                float2 v = make_float2(acc[mt][nt][0], acc[mt][nt][1]);
                *reinterpret_cast<float2*>(g_y + (size_t)row0 * FDIM + col) = v;
            }
            if (row1 < M) {
                float2 v = make_float2(acc[mt][nt][2], acc[mt][nt][3]);
                *reinterpret_cast<float2*>(g_y + (size_t)row1 * FDIM + col) = v;
            }
        }
    }
}

// ---------------------------------------------------------------------------
// CSR gather-aggregate, warp per node. Applies dinv[s] per gathered row and
// dinv[nd] on the self term:  acc = dinv[nd]*y[nd] + sum dinv[s]*y[s].
// FINAL==false: store acc to g_agg (layer 1; gemm2 applies dinv[d]+b1+relu).
// FINAL==true : out = sigmoid(dinv[nd]*acc + b2); cols >= 123 forced to 0.7.
// ---------------------------------------------------------------------------
template <bool FINAL>
__global__ void __launch_bounds__(256)
agg_kernel(const float* __restrict__ b2, float* __restrict__ out, int n) {
    int nd = (int)((blockIdx.x * blockDim.x + threadIdx.x) >> 5);
    int lane = threadIdx.x & 31;
    if (nd >= n) return;
    const int c4 = lane * 4;

    int beg = g_off[nd];
    int end = g_off[nd + 1];
    float dself = g_dinv[nd];

    float4 self = *reinterpret_cast<const float4*>(g_y + (size_t)nd * FDIM + c4);
    float4 acc = make_float4(self.x * dself, self.y * dself,
                             self.z * dself, self.w * dself);
    float4 acc2 = make_float4(0.f, 0.f, 0.f, 0.f);

    int j = beg;
    for (; j + 1 < end; j += 2) {
        int s0 = g_eidx[j];
        int s1 = g_eidx[j + 1];
        float d0 = g_dinv[s0];           // warp-uniform addr -> broadcast
        float d1 = g_dinv[s1];
        float4 v0 = *reinterpret_cast<const float4*>(g_y + (size_t)s0 * FDIM + c4);
        float4 v1 = *reinterpret_cast<const float4*>(g_y + (size_t)s1 * FDIM + c4);
        acc.x = fmaf(v0.x, d0, acc.x); acc.y = fmaf(v0.y, d0, acc.y);
        acc.z = fmaf(v0.z, d0, acc.z); acc.w = fmaf(v0.w, d0, acc.w);
        acc2.x = fmaf(v1.x, d1, acc2.x); acc2.y = fmaf(v1.y, d1, acc2.y);
        acc2.z = fmaf(v1.z, d1, acc2.z); acc2.w = fmaf(v1.w, d1, acc2.w);
    }
    if (j < end) {
        int s0 = g_eidx[j];
        float d0 = g_dinv[s0];
        float4 v0 = *reinterpret_cast<const float4*>(g_y + (size_t)s0 * FDIM + c4);
        acc.x = fmaf(v0.x, d0, acc.x); acc.y = fmaf(v0.y, d0, acc.y);
        acc.z = fmaf(v0.z, d0, acc.z); acc.w = fmaf(v0.w, d0, acc.w);
    }
    acc.x += acc2.x; acc.y += acc2.y; acc.z += acc2.z; acc.w += acc2.w;

    if (!FINAL) {
        *reinterpret_cast<float4*>(g_agg + (size_t)nd * FDIM + c4) = acc;
    } else {
        float4 b = *reinterpret_cast<const float4*>(b2 + c4);
        float4 o;
        float t;
        t = fmaf(acc.x, dself, b.x); o.x = 1.0f / (1.0f + expf(-t));
        t = fmaf(acc.y, dself, b.y); o.y = 1.0f / (1.0f + expf(-t));
        t = fmaf(acc.z, dself, b.z); o.z = 1.0f / (1.0f + expf(-t));
        t = fmaf(acc.w, dself, b.w); o.w = 1.0f / (1.0f + expf(-t));
        if (c4 + 0 >= 123) o.x = 0.7f;
        if (c4 + 1 >= 123) o.y = 0.7f;
        if (c4 + 2 >= 123) o.z = 0.7f;
        if (c4 + 3 >= 123) o.w = 0.7f;
        *reinterpret_cast<float4*>(out + (size_t)nd * FDIM + c4) = o;
    }
}

// ---------------------------------------------------------------------------
extern "C" void kernel_launch(void* const* d_in, const int* in_sizes, int n_in,
                              void* d_out, int out_size) {
    const float* x  = (const float*)d_in[0];
    const void*  ei = d_in[1];
    const float* W1 = (const float*)d_in[2];
    const float* b1 = (const float*)d_in[3];
    const float* W2 = (const float*)d_in[4];
    const float* b2 = (const float*)d_in[5];
    float* out      = (float*)d_out;

    const int N = in_sizes[0] / FDIM;
    const int E = in_sizes[1] / 2;

    // one-time resources (persist across calls; graph-capture safe)
    static cudaStream_t s_side = nullptr;
    static cudaEvent_t ev_fork = nullptr, ev_join = nullptr;
    if (!s_side) {
        cudaStreamCreateWithFlags(&s_side, cudaStreamNonBlocking);
        cudaEventCreateWithFlags(&ev_fork, cudaEventDisableTiming);
        cudaEventCreateWithFlags(&ev_join, cudaEventDisableTiming);
        cudaFuncSetAttribute(gemm_mma_kernel<1>,
                             cudaFuncAttributeMaxDynamicSharedMemorySize, SM_BYTES);
        cudaFuncSetAttribute(gemm_mma_kernel<2>,
                             cudaFuncAttributeMaxDynamicSharedMemorySize, SM_BYTES);
    }

    const int gemm_blocks = (N + 127) / 128;
    const int agg_blocks  = (N + 7) / 8;
    const int eb = (E + 255) / 256;

    // ---- fork: CSR/degree build on side stream ----------------------------
    cudaEventRecord(ev_fork, 0);
    cudaStreamWaitEvent(s_side, ev_fork, 0);
    detect_init_kernel<<<1, 1, 0, s_side>>>();
    detect_zero_kernel<<<eb, 256, 0, s_side>>>(
        (const unsigned long long*)ei, E, (unsigned long long)N, N);
    cnt_accum_kernel<<<eb, 256, 0, s_side>>>(ei, E, N);
    scan_kernel<<<1, 1024, 0, s_side>>>(N);
    place_kernel<<<eb, 256, 0, s_side>>>(ei, E, N);
    cudaEventRecord(ev_join, s_side);

    // ---- main stream: W prep + GEMM1 (independent of CSR) -----------------
    prep_w_kernel<0><<<32, 256>>>(W1);
    prep_w_kernel<1><<<32, 256>>>(W2);
    gemm_mma_kernel<1><<<gemm_blocks, 256, SM_BYTES>>>(x, nullptr, N);

    // ---- join, then aggregation + layer 2 ----------------------------------
    cudaStreamWaitEvent(0, ev_join, 0);
    agg_kernel<false><<<agg_blocks, 256>>>(nullptr, nullptr, N);
    gemm_mma_kernel<2><<<gemm_blocks, 256, SM_BYTES>>>(nullptr, b1, N);
    agg_kernel<true><<<agg_blocks, 256>>>(b2, out, N);
}

// round 12
// speedup vs baseline: 1.2359x; 1.2359x over previous
#include <cuda_runtime.h>
#include <cuda_bf16.h>
#include <cstdint>
#include <cmath>

#define NMAX 100000
#define EMAX 1600000
#define FDIM 128

// ---------------------------------------------------------------------------
// device globals (allocation-free scratch)
// ---------------------------------------------------------------------------
__device__ int   g_is64;
__device__ int   g_cnt[NMAX];
__device__ int   g_off[NMAX + 1];
__device__ int   g_cur[NMAX];
__device__ int   g_eidx[EMAX];
__device__ int   g_bsum[128];     // per-block partial sums (scan pass 1)
__device__ int   g_bbase[128];    // per-block exclusive bases (scan pass 2)
__device__ float g_dinv[NMAX];
__device__ float g_y[(size_t)NMAX * FDIM];
__device__ float g_agg[(size_t)NMAX * FDIM];
// pre-split W as bf16 pairs, plain [k][n/2] uint32 layout (128 x 64), 2 slots
__device__ __align__(16) uint32_t g_Whi[2][8192];
__device__ __align__(16) uint32_t g_Wlo[2][8192];

// ---------------------------------------------------------------------------
// warp-level MMA helpers (sm_80+ ISA: safe for plain sm_103 target)
// ---------------------------------------------------------------------------
__device__ __forceinline__ uint32_t smem_to_u32(const void* p) {
    uint32_t a;
    asm("{ .reg .u64 t; cvta.to.shared.u64 t, %1; cvt.u32.u64 %0, t; }"
        : "=r"(a) : "l"(p));
    return a;
}

#define LDSM_X4(r0, r1, r2, r3, addr) \
    asm volatile("ldmatrix.sync.aligned.m8n8.x4.shared.b16 {%0,%1,%2,%3}, [%4];" \
                 : "=r"(r0), "=r"(r1), "=r"(r2), "=r"(r3) : "r"(addr))
#define LDSM_X4_T(r0, r1, r2, r3, addr) \
    asm volatile("ldmatrix.sync.aligned.m8n8.x4.trans.shared.b16 {%0,%1,%2,%3}, [%4];" \
                 : "=r"(r0), "=r"(r1), "=r"(r2), "=r"(r3) : "r"(addr))

__device__ __forceinline__ void mma16816(float* c, const uint32_t* a,
                                         const uint32_t* b) {
    asm volatile(
        "mma.sync.aligned.m16n8k16.row.col.f32.bf16.bf16.f32 "
        "{%0,%1,%2,%3}, {%4,%5,%6,%7}, {%8,%9}, {%0,%1,%2,%3};"
        : "+f"(c[0]), "+f"(c[1]), "+f"(c[2]), "+f"(c[3])
        : "r"(a[0]), "r"(a[1]), "r"(a[2]), "r"(a[3]), "r"(b[0]), "r"(b[1]));
}

// ---------------------------------------------------------------------------
// index dtype detection (+ fused g_cnt zeroing: E >> N so grid covers both)
// ---------------------------------------------------------------------------
__global__ void detect_init_kernel() { g_is64 = 1; }
__global__ void detect_zero_kernel(const unsigned long long* __restrict__ ei,
                                   int E, unsigned long long n64, int n) {
    int i = blockIdx.x * blockDim.x + threadIdx.x;
    if (i < n) g_cnt[i] = 0;
    if (i < E && ei[i] >= n64) g_is64 = 0;
}
__device__ __forceinline__ int load_idx(const void* ei, int i) {
    if (g_is64) return (int)((const long long*)ei)[i];
    return ((const int*)ei)[i];
}

// ---------------------------------------------------------------------------
// CSR build
// ---------------------------------------------------------------------------
__global__ void cnt_accum_kernel(const void* __restrict__ ei, int E, int n) {
    int e = blockIdx.x * blockDim.x + threadIdx.x;
    if (e < E) {
        int d = load_idx(ei, E + e);
        if ((unsigned)d < (unsigned)n) atomicAdd(&g_cnt[d], 1);
    }
}

// scan pass 1: per-block sums (1024 elems/block) + fused dinv
__global__ void __launch_bounds__(1024)
scan1_kernel(int n) {
    __shared__ int wsum[32];
    const int tid = threadIdx.x, lane = tid & 31, w = tid >> 5;
    int i = blockIdx.x * 1024 + tid;
    int v = (i < n) ? g_cnt[i] : 0;
    if (i < n) g_dinv[i] = rsqrtf((float)(v + 1));
    int s = v;
#pragma unroll
    for (int off = 16; off > 0; off >>= 1)
        s += __shfl_down_sync(0xffffffffu, s, off);
    if (lane == 0) wsum[w] = s;
    __syncthreads();
    if (w == 0) {
        int t = wsum[lane];
#pragma unroll
        for (int off = 16; off > 0; off >>= 1)
            t += __shfl_down_sync(0xffffffffu, t, off);
        if (lane == 0) g_bsum[blockIdx.x] = t;
    }
}

// scan pass 2: exclusive scan of <=128 block partials; writes g_off[n]=total
__global__ void __launch_bounds__(128)
scan2_kernel(int nb, int n) {
    __shared__ int ws[4];
    const int tid = threadIdx.x, lane = tid & 31, w = tid >> 5;
    int v = (tid < nb) ? g_bsum[tid] : 0;
    int s = v;
#pragma unroll
    for (int off = 1; off < 32; off <<= 1) {
        int t = __shfl_up_sync(0xffffffffu, s, off);
        if (lane >= off) s += t;
    }
    if (lane == 31) ws[w] = s;
    __syncthreads();
    int add = 0;
#pragma unroll
    for (int k = 0; k < 4; k++)
        if (k < w) add += ws[k];
    int incl = s + add;
    if (tid < nb) g_bbase[tid] = incl - v;   // exclusive base
    if (tid == nb - 1) g_off[n] = incl;      // grand total
}

// scan pass 3: block-local exclusive scan + base -> g_off/g_cur
__global__ void __launch_bounds__(1024)
scan3_kernel(int n) {
    __shared__ int wsum[32];
    const int tid = threadIdx.x, lane = tid & 31, w = tid >> 5;
    int i = blockIdx.x * 1024 + tid;
    int v = (i < n) ? g_cnt[i] : 0;
    int s = v;
#pragma unroll
    for (int off = 1; off < 32; off <<= 1) {
        int t = __shfl_up_sync(0xffffffffu, s, off);
        if (lane >= off) s += t;
    }
    if (lane == 31) wsum[w] = s;
    __syncthreads();
    if (w == 0) {
        int t = wsum[lane];
#pragma unroll
        for (int off = 1; off < 32; off <<= 1) {
            int u = __shfl_up_sync(0xffffffffu, t, off);
            if (lane >= off) t += u;
        }
        wsum[lane] = t;
    }
    __syncthreads();
    int excl = (s - v) + ((w > 0) ? wsum[w - 1] : 0) + g_bbase[blockIdx.x];
    if (i < n) {
        g_off[i] = excl;
        g_cur[i] = excl;
    }
}

__global__ void place_kernel(const void* __restrict__ ei, int E, int n) {
    int e = blockIdx.x * blockDim.x + threadIdx.x;
    if (e >= E) return;
    int s = load_idx(ei, e);
    int d = load_idx(ei, E + e);
    if ((unsigned)s >= (unsigned)n || (unsigned)d >= (unsigned)n) return;
    int p = atomicAdd(&g_cur[d], 1);
    g_eidx[p] = s;
}

// ---------------------------------------------------------------------------
// W prep: split W (fp32 [K=128, N=128]) into bf16 hi/lo pairs along n,
// plain [k][n/2] uint32 layout, into slot SLOT.
// ---------------------------------------------------------------------------
template <int SLOT>
__global__ void __launch_bounds__(256)
prep_w_kernel(const float* __restrict__ W) {
    int j = blockIdx.x * blockDim.x + threadIdx.x;  // 0..8191
    if (j >= 8192) return;
    int k = j >> 6;
    int np = (j & 63) * 2;
    float w0 = W[(size_t)k * FDIM + np];
    float w1 = W[(size_t)k * FDIM + np + 1];
    __nv_bfloat16 h0 = __float2bfloat16(w0);
    __nv_bfloat16 h1 = __float2bfloat16(w1);
    __nv_bfloat16 l0 = __float2bfloat16(w0 - __bfloat162float(h0));
    __nv_bfloat16 l1 = __float2bfloat16(w1 - __bfloat162float(h1));
    g_Whi[SLOT][j] = (uint32_t)__bfloat16_as_ushort(h0) |
                     ((uint32_t)__bfloat16_as_ushort(h1) << 16);
    g_Wlo[SLOT][j] = (uint32_t)__bfloat16_as_ushort(l0) |
                     ((uint32_t)__bfloat16_as_ushort(l1) << 16);
}

// ---------------------------------------------------------------------------
// HMMA GEMM: y_row = act(A_row) @ W (NO dinv scaling — deferred to agg).
// fp32 via bf16 3-term split (Ahi*Bhi + Alo*Bhi + Ahi*Blo).
// 128x128 tile/CTA, 8 warps (4x2), K=128.
// LAYER==1: A = X (no dinv/CSR dependency at all!)
// LAYER==2: A = g_agg, act = relu(a*dinv[row] + b1[k]).
// ---------------------------------------------------------------------------
#define SSTRIDE 136   // bf16 elements per smem row (128 + 8 pad)
#define SM_AH 0
#define SM_AL (128 * SSTRIDE)
#define SM_BH (2 * 128 * SSTRIDE)
#define SM_BL (3 * 128 * SSTRIDE)
#define SM_ELEMS (4 * 128 * SSTRIDE)
#define SM_BYTES (SM_ELEMS * 2)

template <int LAYER>
__global__ void __launch_bounds__(256)
gemm_mma_kernel(const float* __restrict__ X,
                const float* __restrict__ bin, int M) {
    extern __shared__ __align__(16) char smem_raw[];
    __nv_bfloat16* sm = reinterpret_cast<__nv_bfloat16*>(smem_raw);
    const uint32_t sbase = smem_to_u32(smem_raw);

    const int tid = threadIdx.x;
    const int wid = tid >> 5;
    const int lane = tid & 31;
    const int warp_m = wid & 3;       // 4 m-strips of 32 rows
    const int warp_n = wid >> 2;      // 2 n-strips of 64 cols
    const int block_row = blockIdx.x * 128;

    const float* Aptr = (LAYER == 1) ? X : (const float*)g_agg;
    const uint32_t* Bhi = g_Whi[LAYER - 1];
    const uint32_t* Blo = g_Wlo[LAYER - 1];

    // --- load A (fp32), activation, split hi/lo into padded smem -----------
#pragma unroll
    for (int i = 0; i < 16; i++) {
        int f4 = tid + i * 256;           // 4096 float4s
        int row = f4 >> 5;
        int c4 = (f4 & 31) * 4;
        int grow = block_row + row;
        float4 av = make_float4(0.f, 0.f, 0.f, 0.f);
        if (grow < M) {
            av = *reinterpret_cast<const float4*>(Aptr + (size_t)grow * FDIM + c4);
            if (LAYER == 2) {
                float dv = g_dinv[grow];
                av.x = fmaxf(fmaf(av.x, dv, bin[c4 + 0]), 0.0f);
                av.y = fmaxf(fmaf(av.y, dv, bin[c4 + 1]), 0.0f);
                av.z = fmaxf(fmaf(av.z, dv, bin[c4 + 2]), 0.0f);
                av.w = fmaxf(fmaf(av.w, dv, bin[c4 + 3]), 0.0f);
            }
        }
        __nv_bfloat16 hx = __float2bfloat16(av.x), hy = __float2bfloat16(av.y);
        __nv_bfloat16 hz = __float2bfloat16(av.z), hw = __float2bfloat16(av.w);
        __nv_bfloat16 lx = __float2bfloat16(av.x - __bfloat162float(hx));
        __nv_bfloat16 ly = __float2bfloat16(av.y - __bfloat162float(hy));
        __nv_bfloat16 lz = __float2bfloat16(av.z - __bfloat162float(hz));
        __nv_bfloat16 lw = __float2bfloat16(av.w - __bfloat162float(hw));
        uint32_t* ah = reinterpret_cast<uint32_t*>(sm + SM_AH + row * SSTRIDE + c4);
        uint32_t* al = reinterpret_cast<uint32_t*>(sm + SM_AL + row * SSTRIDE + c4);
        ah[0] = (uint32_t)__bfloat16_as_ushort(hx) | ((uint32_t)__bfloat16_as_ushort(hy) << 16);
        ah[1] = (uint32_t)__bfloat16_as_ushort(hz) | ((uint32_t)__bfloat16_as_ushort(hw) << 16);
        al[0] = (uint32_t)__bfloat16_as_ushort(lx) | ((uint32_t)__bfloat16_as_ushort(ly) << 16);
        al[1] = (uint32_t)__bfloat16_as_ushort(lz) | ((uint32_t)__bfloat16_as_ushort(lw) << 16);
    }

    // --- copy pre-split B into padded smem (uint4 = 8 bf16) ----------------
#pragma unroll
    for (int i = 0; i < 8; i++) {
        int u = tid + i * 256;            // 2048 uint4 per variant
        int row = u >> 4;
        int c8 = (u & 15) * 8;
        *reinterpret_cast<uint4*>(sm + SM_BH + row * SSTRIDE + c8) =
            *(reinterpret_cast<const uint4*>(Bhi) + u);
        *reinterpret_cast<uint4*>(sm + SM_BL + row * SSTRIDE + c8) =
            *(reinterpret_cast<const uint4*>(Blo) + u);
    }
    __syncthreads();

    // --- main MMA loop ------------------------------------------------------
    float acc[2][8][4];
#pragma unroll
    for (int mt = 0; mt < 2; mt++)
#pragma unroll
        for (int nt = 0; nt < 8; nt++)
#pragma unroll
            for (int q = 0; q < 4; q++) acc[mt][nt][q] = 0.0f;

    const int lrow = lane & 15;
    const int lcol = (lane >> 4) * 8;

#pragma unroll
    for (int ks = 0; ks < 8; ks++) {
        uint32_t ah[2][4], al[2][4], bf[4][4];
#pragma unroll
        for (int mt = 0; mt < 2; mt++) {
            int row = warp_m * 32 + mt * 16 + lrow;
            int col = ks * 16 + lcol;
            uint32_t addr_h = sbase + (uint32_t)((SM_AH + row * SSTRIDE + col) * 2);
            uint32_t addr_l = sbase + (uint32_t)((SM_AL + row * SSTRIDE + col) * 2);
            LDSM_X4(ah[mt][0], ah[mt][1], ah[mt][2], ah[mt][3], addr_h);
            LDSM_X4(al[mt][0], al[mt][1], al[mt][2], al[mt][3], addr_l);
        }
#pragma unroll
        for (int np = 0; np < 4; np++) {
            int r = ks * 16 + lrow;
            int c = warp_n * 64 + np * 16 + lcol;
            uint32_t addr = sbase + (uint32_t)((SM_BH + r * SSTRIDE + c) * 2);
            LDSM_X4_T(bf[np][0], bf[np][1], bf[np][2], bf[np][3], addr);
        }
#pragma unroll
        for (int mt = 0; mt < 2; mt++)
#pragma unroll
            for (int np = 0; np < 4; np++) {
                mma16816(acc[mt][np * 2 + 0], ah[mt], &bf[np][0]);
                mma16816(acc[mt][np * 2 + 1], ah[mt], &bf[np][2]);
                mma16816(acc[mt][np * 2 + 0], al[mt], &bf[np][0]);
                mma16816(acc[mt][np * 2 + 1], al[mt], &bf[np][2]);
            }
#pragma unroll
        for (int np = 0; np < 4; np++) {
            int r = ks * 16 + lrow;
            int c = warp_n * 64 + np * 16 + lcol;
            uint32_t addr = sbase + (uint32_t)((SM_BL + r * SSTRIDE + c) * 2);
            LDSM_X4_T(bf[np][0], bf[np][1], bf[np][2], bf[np][3], addr);
        }
#pragma unroll
        for (int mt = 0; mt < 2; mt++)
#pragma unroll
            for (int np = 0; np < 4; np++) {
                mma16816(acc[mt][np * 2 + 0], ah[mt], &bf[np][0]);
                mma16816(acc[mt][np * 2 + 1], ah[mt], &bf[np][2]);
            }
    }

    // --- epilogue: store raw y (dinv applied later in agg) ------------------
    const int er0 = lane >> 2;            // 0..7
    const int ec = (lane & 3) * 2;
#pragma unroll
    for (int mt = 0; mt < 2; mt++) {
        int row0 = block_row + warp_m * 32 + mt * 16 + er0;
        int row1 = row0 + 8;
#pragma unroll
        for (int nt = 0; nt < 8; nt++) {
            int col = warp_n * 64 + nt * 8 + ec;
            if (row0 < M) {
                float2 v = make_float2(acc[mt][nt][0], acc[mt][nt][1]);
                *reinterpret_cast<float2*>(g_y + (size_t)row0 * FDIM + col) = v;
            }
            if (row1 < M) {
                float2 v = make_float2(acc[mt][nt][2], acc[mt][nt][3]);
                *reinterpret_cast<float2*>(g_y + (size_t)row1 * FDIM + col) = v;
            }
        }
    }
}

// ---------------------------------------------------------------------------
// CSR gather-aggregate, warp per node. Applies dinv[s] per gathered row and
// dinv[nd] on the self term:  acc = dinv[nd]*y[nd] + sum dinv[s]*y[s].
// FINAL==false: store acc to g_agg (layer 1; gemm2 applies dinv[d]+b1+relu).
// FINAL==true : out = sigmoid(dinv[nd]*acc + b2); cols >= 123 forced to 0.7.
// ---------------------------------------------------------------------------
template <bool FINAL>
__global__ void __launch_bounds__(256)
agg_kernel(const float* __restrict__ b2, float* __restrict__ out, int n) {
    int nd = (int)((blockIdx.x * blockDim.x + threadIdx.x) >> 5);
    int lane = threadIdx.x & 31;
    if (nd >= n) return;
    const int c4 = lane * 4;

    int beg = g_off[nd];
    int end = g_off[nd + 1];
    float dself = g_dinv[nd];

    float4 self = *reinterpret_cast<const float4*>(g_y + (size_t)nd * FDIM + c4);
    float4 acc = make_float4(self.x * dself, self.y * dself,
                             self.z * dself, self.w * dself);
    float4 acc2 = make_float4(0.f, 0.f, 0.f, 0.f);

    int j = beg;
    for (; j + 1 < end; j += 2) {
        int s0 = g_eidx[j];
        int s1 = g_eidx[j + 1];
        float d0 = g_dinv[s0];           // warp-uniform addr -> broadcast
        float d1 = g_dinv[s1];
        float4 v0 = *reinterpret_cast<const float4*>(g_y + (size_t)s0 * FDIM + c4);
        float4 v1 = *reinterpret_cast<const float4*>(g_y + (size_t)s1 * FDIM + c4);
        acc.x = fmaf(v0.x, d0, acc.x); acc.y = fmaf(v0.y, d0, acc.y);
        acc.z = fmaf(v0.z, d0, acc.z); acc.w = fmaf(v0.w, d0, acc.w);
        acc2.x = fmaf(v1.x, d1, acc2.x); acc2.y = fmaf(v1.y, d1, acc2.y);
        acc2.z = fmaf(v1.z, d1, acc2.z); acc2.w = fmaf(v1.w, d1, acc2.w);
    }
    if (j < end) {
        int s0 = g_eidx[j];
        float d0 = g_dinv[s0];
        float4 v0 = *reinterpret_cast<const float4*>(g_y + (size_t)s0 * FDIM + c4);
        acc.x = fmaf(v0.x, d0, acc.x); acc.y = fmaf(v0.y, d0, acc.y);
        acc.z = fmaf(v0.z, d0, acc.z); acc.w = fmaf(v0.w, d0, acc.w);
    }
    acc.x += acc2.x; acc.y += acc2.y; acc.z += acc2.z; acc.w += acc2.w;

    if (!FINAL) {
        *reinterpret_cast<float4*>(g_agg + (size_t)nd * FDIM + c4) = acc;
    } else {
        float4 b = *reinterpret_cast<const float4*>(b2 + c4);
        float4 o;
        float t;
        t = fmaf(acc.x, dself, b.x); o.x = 1.0f / (1.0f + expf(-t));
        t = fmaf(acc.y, dself, b.y); o.y = 1.0f / (1.0f + expf(-t));
        t = fmaf(acc.z, dself, b.z); o.z = 1.0f / (1.0f + expf(-t));
        t = fmaf(acc.w, dself, b.w); o.w = 1.0f / (1.0f + expf(-t));
        if (c4 + 0 >= 123) o.x = 0.7f;
        if (c4 + 1 >= 123) o.y = 0.7f;
        if (c4 + 2 >= 123) o.z = 0.7f;
        if (c4 + 3 >= 123) o.w = 0.7f;
        *reinterpret_cast<float4*>(out + (size_t)nd * FDIM + c4) = o;
    }
}

// ---------------------------------------------------------------------------
extern "C" void kernel_launch(void* const* d_in, const int* in_sizes, int n_in,
                              void* d_out, int out_size) {
    const float* x  = (const float*)d_in[0];
    const void*  ei = d_in[1];
    const float* W1 = (const float*)d_in[2];
    const float* b1 = (const float*)d_in[3];
    const float* W2 = (const float*)d_in[4];
    const float* b2 = (const float*)d_in[5];
    float* out      = (float*)d_out;

    const int N = in_sizes[0] / FDIM;
    const int E = in_sizes[1] / 2;

    // one-time resources (persist across calls; graph-capture safe)
    static cudaStream_t s_side = nullptr;
    static cudaEvent_t ev_fork = nullptr, ev_join = nullptr;
    if (!s_side) {
        cudaStreamCreateWithFlags(&s_side, cudaStreamNonBlocking);
        cudaEventCreateWithFlags(&ev_fork, cudaEventDisableTiming);
        cudaEventCreateWithFlags(&ev_join, cudaEventDisableTiming);
        cudaFuncSetAttribute(gemm_mma_kernel<1>,
                             cudaFuncAttributeMaxDynamicSharedMemorySize, SM_BYTES);
        cudaFuncSetAttribute(gemm_mma_kernel<2>,
                             cudaFuncAttributeMaxDynamicSharedMemorySize, SM_BYTES);
    }

    const int gemm_blocks = (N + 127) / 128;
    const int agg_blocks  = (N + 7) / 8;
    const int eb = (E + 255) / 256;
    const int nb = (N + 1023) / 1024;   // scan blocks (<=128 for N<=131072)

    // ---- fork: CSR/degree build on side stream ----------------------------
    cudaEventRecord(ev_fork, 0);
    cudaStreamWaitEvent(s_side, ev_fork, 0);
    detect_init_kernel<<<1, 1, 0, s_side>>>();
    detect_zero_kernel<<<eb, 256, 0, s_side>>>(
        (const unsigned long long*)ei, E, (unsigned long long)N, N);
    cnt_accum_kernel<<<eb, 256, 0, s_side>>>(ei, E, N);
    scan1_kernel<<<nb, 1024, 0, s_side>>>(N);
    scan2_kernel<<<1, 128, 0, s_side>>>(nb, N);
    scan3_kernel<<<nb, 1024, 0, s_side>>>(N);
    place_kernel<<<eb, 256, 0, s_side>>>(ei, E, N);
    cudaEventRecord(ev_join, s_side);

    // ---- main stream: W prep + GEMM1 (independent of CSR) -----------------
    prep_w_kernel<0><<<32, 256>>>(W1);
    prep_w_kernel<1><<<32, 256>>>(W2);
    gemm_mma_kernel<1><<<gemm_blocks, 256, SM_BYTES>>>(x, nullptr, N);

    // ---- join, then aggregation + layer 2 ----------------------------------
    cudaStreamWaitEvent(0, ev_join, 0);
    agg_kernel<false><<<agg_blocks, 256>>>(nullptr, nullptr, N);
    gemm_mma_kernel<2><<<gemm_blocks, 256, SM_BYTES>>>(nullptr, b1, N);
    agg_kernel<true><<<agg_blocks, 256>>>(b2, out, N);
}

// round 13
// speedup vs baseline: 1.3436x; 1.0871x over previous
#include <cuda_runtime.h>
#include <cuda_bf16.h>
#include <cuda_fp16.h>
#include <cstdint>
#include <cmath>

#define NMAX 100000
#define EMAX 1600000
#define FDIM 128

// ---------------------------------------------------------------------------
// device globals (allocation-free scratch)
// ---------------------------------------------------------------------------
__device__ int   g_is64;
__device__ int   g_cnt[NMAX];
__device__ int   g_off[NMAX + 1];
__device__ int   g_cur[NMAX];
__device__ int   g_eidx[EMAX];
__device__ int   g_bsum[128];     // per-block partial sums (scan pass 1)
__device__ int   g_bbase[128];    // per-block exclusive bases (scan pass 2)
__device__ float g_dinv[NMAX];
__device__ __align__(16) __half g_yh[(size_t)NMAX * FDIM];  // y in fp16 (gather)
__device__ float g_agg[(size_t)NMAX * FDIM];                // fp32 aggregate
// pre-split W as bf16 pairs, plain [k][n/2] uint32 layout (128 x 64), 2 slots
__device__ __align__(16) uint32_t g_Whi[2][8192];
__device__ __align__(16) uint32_t g_Wlo[2][8192];

// ---------------------------------------------------------------------------
// warp-level MMA helpers (sm_80+ ISA: safe for plain sm_103 target)
// ---------------------------------------------------------------------------
__device__ __forceinline__ uint32_t smem_to_u32(const void* p) {
    uint32_t a;
    asm("{ .reg .u64 t; cvta.to.shared.u64 t, %1; cvt.u32.u64 %0, t; }"
        : "=r"(a) : "l"(p));
    return a;
}

#define LDSM_X4(r0, r1, r2, r3, addr) \
    asm volatile("ldmatrix.sync.aligned.m8n8.x4.shared.b16 {%0,%1,%2,%3}, [%4];" \
                 : "=r"(r0), "=r"(r1), "=r"(r2), "=r"(r3) : "r"(addr))
#define LDSM_X4_T(r0, r1, r2, r3, addr) \
    asm volatile("ldmatrix.sync.aligned.m8n8.x4.trans.shared.b16 {%0,%1,%2,%3}, [%4];" \
                 : "=r"(r0), "=r"(r1), "=r"(r2), "=r"(r3) : "r"(addr))

__device__ __forceinline__ void mma16816(float* c, const uint32_t* a,
                                         const uint32_t* b) {
    asm volatile(
        "mma.sync.aligned.m16n8k16.row.col.f32.bf16.bf16.f32 "
        "{%0,%1,%2,%3}, {%4,%5,%6,%7}, {%8,%9}, {%0,%1,%2,%3};"
        : "+f"(c[0]), "+f"(c[1]), "+f"(c[2]), "+f"(c[3])
        : "r"(a[0]), "r"(a[1]), "r"(a[2]), "r"(a[3]), "r"(b[0]), "r"(b[1]));
}

// ---------------------------------------------------------------------------
// index dtype detection (+ fused g_cnt zeroing: E >> N so grid covers both)
// ---------------------------------------------------------------------------
__global__ void detect_init_kernel() { g_is64 = 1; }
__global__ void detect_zero_kernel(const unsigned long long* __restrict__ ei,
                                   int E, unsigned long long n64, int n) {
    int i = blockIdx.x * blockDim.x + threadIdx.x;
    if (i < n) g_cnt[i] = 0;
    if (i < E && ei[i] >= n64) g_is64 = 0;
}
__device__ __forceinline__ int load_idx(const void* ei, int i) {
    if (g_is64) return (int)((const long long*)ei)[i];
    return ((const int*)ei)[i];
}

// ---------------------------------------------------------------------------
// CSR build
// ---------------------------------------------------------------------------
__global__ void cnt_accum_kernel(const void* __restrict__ ei, int E, int n) {
    int e = blockIdx.x * blockDim.x + threadIdx.x;
    if (e < E) {
        int d = load_idx(ei, E + e);
        if ((unsigned)d < (unsigned)n) atomicAdd(&g_cnt[d], 1);
    }
}

// scan pass 1: per-block sums (1024 elems/block) + fused dinv
__global__ void __launch_bounds__(1024)
scan1_kernel(int n) {
    __shared__ int wsum[32];
    const int tid = threadIdx.x, lane = tid & 31, w = tid >> 5;
    int i = blockIdx.x * 1024 + tid;
    int v = (i < n) ? g_cnt[i] : 0;
    if (i < n) g_dinv[i] = rsqrtf((float)(v + 1));
    int s = v;
#pragma unroll
    for (int off = 16; off > 0; off >>= 1)
        s += __shfl_down_sync(0xffffffffu, s, off);
    if (lane == 0) wsum[w] = s;
    __syncthreads();
    if (w == 0) {
        int t = wsum[lane];
#pragma unroll
        for (int off = 16; off > 0; off >>= 1)
            t += __shfl_down_sync(0xffffffffu, t, off);
        if (lane == 0) g_bsum[blockIdx.x] = t;
    }
}

// scan pass 2: exclusive scan of <=128 block partials; writes g_off[n]=total
__global__ void __launch_bounds__(128)
scan2_kernel(int nb, int n) {
    __shared__ int ws[4];
    const int tid = threadIdx.x, lane = tid & 31, w = tid >> 5;
    int v = (tid < nb) ? g_bsum[tid] : 0;
    int s = v;
#pragma unroll
    for (int off = 1; off < 32; off <<= 1) {
        int t = __shfl_up_sync(0xffffffffu, s, off);
        if (lane >= off) s += t;
    }
    if (lane == 31) ws[w] = s;
    __syncthreads();
    int add = 0;
#pragma unroll
    for (int k = 0; k < 4; k++)
        if (k < w) add += ws[k];
    int incl = s + add;
    if (tid < nb) g_bbase[tid] = incl - v;   // exclusive base
    if (tid == nb - 1) g_off[n] = incl;      // grand total
}

// scan pass 3: block-local exclusive scan + base -> g_off/g_cur
__global__ void __launch_bounds__(1024)
scan3_kernel(int n) {
    __shared__ int wsum[32];
    const int tid = threadIdx.x, lane = tid & 31, w = tid >> 5;
    int i = blockIdx.x * 1024 + tid;
    int v = (i < n) ? g_cnt[i] : 0;
    int s = v;
#pragma unroll
    for (int off = 1; off < 32; off <<= 1) {
        int t = __shfl_up_sync(0xffffffffu, s, off);
        if (lane >= off) s += t;
    }
    if (lane == 31) wsum[w] = s;
    __syncthreads();
    if (w == 0) {
        int t = wsum[lane];
#pragma unroll
        for (int off = 1; off < 32; off <<= 1) {
            int u = __shfl_up_sync(0xffffffffu, t, off);
            if (lane >= off) t += u;
        }
        wsum[lane] = t;
    }
    __syncthreads();
    int excl = (s - v) + ((w > 0) ? wsum[w - 1] : 0) + g_bbase[blockIdx.x];
    if (i < n) {
        g_off[i] = excl;
        g_cur[i] = excl;
    }
}

__global__ void place_kernel(const void* __restrict__ ei, int E, int n) {
    int e = blockIdx.x * blockDim.x + threadIdx.x;
    if (e >= E) return;
    int s = load_idx(ei, e);
    int d = load_idx(ei, E + e);
    if ((unsigned)s >= (unsigned)n || (unsigned)d >= (unsigned)n) return;
    int p = atomicAdd(&g_cur[d], 1);
    g_eidx[p] = s;
}

// ---------------------------------------------------------------------------
// W prep: split W (fp32 [K=128, N=128]) into bf16 hi/lo pairs along n,
// plain [k][n/2] uint32 layout, into slot SLOT.
// ---------------------------------------------------------------------------
template <int SLOT>
__global__ void __launch_bounds__(256)
prep_w_kernel(const float* __restrict__ W) {
    int j = blockIdx.x * blockDim.x + threadIdx.x;  // 0..8191
    if (j >= 8192) return;
    int k = j >> 6;
    int np = (j & 63) * 2;
    float w0 = W[(size_t)k * FDIM + np];
    float w1 = W[(size_t)k * FDIM + np + 1];
    __nv_bfloat16 h0 = __float2bfloat16(w0);
    __nv_bfloat16 h1 = __float2bfloat16(w1);
    __nv_bfloat16 l0 = __float2bfloat16(w0 - __bfloat162float(h0));
    __nv_bfloat16 l1 = __float2bfloat16(w1 - __bfloat162float(h1));
    g_Whi[SLOT][j] = (uint32_t)__bfloat16_as_ushort(h0) |
                     ((uint32_t)__bfloat16_as_ushort(h1) << 16);
    g_Wlo[SLOT][j] = (uint32_t)__bfloat16_as_ushort(l0) |
                     ((uint32_t)__bfloat16_as_ushort(l1) << 16);
}

// ---------------------------------------------------------------------------
// HMMA GEMM: y_row = act(A_row) @ W (dinv deferred to agg), y stored fp16.
// fp32 accum via bf16 3-term split (Ahi*Bhi + Alo*Bhi + Ahi*Blo).
// 128x128 tile/CTA, 8 warps (4x2), K=128.
// LAYER==1: A = X; LAYER==2: A = g_agg, act = relu(a*dinv[row] + b1[k]).
// ---------------------------------------------------------------------------
#define SSTRIDE 136   // bf16 elements per smem row (128 + 8 pad)
#define SM_AH 0
#define SM_AL (128 * SSTRIDE)
#define SM_BH (2 * 128 * SSTRIDE)
#define SM_BL (3 * 128 * SSTRIDE)
#define SM_ELEMS (4 * 128 * SSTRIDE)
#define SM_BYTES (SM_ELEMS * 2)

template <int LAYER>
__global__ void __launch_bounds__(256)
gemm_mma_kernel(const float* __restrict__ X,
                const float* __restrict__ bin, int M) {
    extern __shared__ __align__(16) char smem_raw[];
    __nv_bfloat16* sm = reinterpret_cast<__nv_bfloat16*>(smem_raw);
    const uint32_t sbase = smem_to_u32(smem_raw);

    const int tid = threadIdx.x;
    const int wid = tid >> 5;
    const int lane = tid & 31;
    const int warp_m = wid & 3;       // 4 m-strips of 32 rows
    const int warp_n = wid >> 2;      // 2 n-strips of 64 cols
    const int block_row = blockIdx.x * 128;

    const float* Aptr = (LAYER == 1) ? X : (const float*)g_agg;
    const uint32_t* Bhi = g_Whi[LAYER - 1];
    const uint32_t* Blo = g_Wlo[LAYER - 1];

    // --- load A (fp32), activation, split hi/lo into padded smem -----------
#pragma unroll
    for (int i = 0; i < 16; i++) {
        int f4 = tid + i * 256;           // 4096 float4s
        int row = f4 >> 5;
        int c4 = (f4 & 31) * 4;
        int grow = block_row + row;
        float4 av = make_float4(0.f, 0.f, 0.f, 0.f);
        if (grow < M) {
            av = *reinterpret_cast<const float4*>(Aptr + (size_t)grow * FDIM + c4);
            if (LAYER == 2) {
                float dv = g_dinv[grow];
                av.x = fmaxf(fmaf(av.x, dv, bin[c4 + 0]), 0.0f);
                av.y = fmaxf(fmaf(av.y, dv, bin[c4 + 1]), 0.0f);
                av.z = fmaxf(fmaf(av.z, dv, bin[c4 + 2]), 0.0f);
                av.w = fmaxf(fmaf(av.w, dv, bin[c4 + 3]), 0.0f);
            }
        }
        __nv_bfloat16 hx = __float2bfloat16(av.x), hy = __float2bfloat16(av.y);
        __nv_bfloat16 hz = __float2bfloat16(av.z), hw = __float2bfloat16(av.w);
        __nv_bfloat16 lx = __float2bfloat16(av.x - __bfloat162float(hx));
        __nv_bfloat16 ly = __float2bfloat16(av.y - __bfloat162float(hy));
        __nv_bfloat16 lz = __float2bfloat16(av.z - __bfloat162float(hz));
        __nv_bfloat16 lw = __float2bfloat16(av.w - __bfloat162float(hw));
        uint32_t* ah = reinterpret_cast<uint32_t*>(sm + SM_AH + row * SSTRIDE + c4);
        uint32_t* al = reinterpret_cast<uint32_t*>(sm + SM_AL + row * SSTRIDE + c4);
        ah[0] = (uint32_t)__bfloat16_as_ushort(hx) | ((uint32_t)__bfloat16_as_ushort(hy) << 16);
        ah[1] = (uint32_t)__bfloat16_as_ushort(hz) | ((uint32_t)__bfloat16_as_ushort(hw) << 16);
        al[0] = (uint32_t)__bfloat16_as_ushort(lx) | ((uint32_t)__bfloat16_as_ushort(ly) << 16);
        al[1] = (uint32_t)__bfloat16_as_ushort(lz) | ((uint32_t)__bfloat16_as_ushort(lw) << 16);
    }

    // --- copy pre-split B into padded smem (uint4 = 8 bf16) ----------------
#pragma unroll
    for (int i = 0; i < 8; i++) {
        int u = tid + i * 256;            // 2048 uint4 per variant
        int row = u >> 4;
        int c8 = (u & 15) * 8;
        *reinterpret_cast<uint4*>(sm + SM_BH + row * SSTRIDE + c8) =
            *(reinterpret_cast<const uint4*>(Bhi) + u);
        *reinterpret_cast<uint4*>(sm + SM_BL + row * SSTRIDE + c8) =
            *(reinterpret_cast<const uint4*>(Blo) + u);
    }
    __syncthreads();

    // --- main MMA loop ------------------------------------------------------
    float acc[2][8][4];
#pragma unroll
    for (int mt = 0; mt < 2; mt++)
#pragma unroll
        for (int nt = 0; nt < 8; nt++)
#pragma unroll
            for (int q = 0; q < 4; q++) acc[mt][nt][q] = 0.0f;

    const int lrow = lane & 15;
    const int lcol = (lane >> 4) * 8;

#pragma unroll
    for (int ks = 0; ks < 8; ks++) {
        uint32_t ah[2][4], al[2][4], bf[4][4];
#pragma unroll
        for (int mt = 0; mt < 2; mt++) {
            int row = warp_m * 32 + mt * 16 + lrow;
            int col = ks * 16 + lcol;
            uint32_t addr_h = sbase + (uint32_t)((SM_AH + row * SSTRIDE + col) * 2);
            uint32_t addr_l = sbase + (uint32_t)((SM_AL + row * SSTRIDE + col) * 2);
            LDSM_X4(ah[mt][0], ah[mt][1], ah[mt][2], ah[mt][3], addr_h);
            LDSM_X4(al[mt][0], al[mt][1], al[mt][2], al[mt][3], addr_l);
        }
#pragma unroll
        for (int np = 0; np < 4; np++) {
            int r = ks * 16 + lrow;
            int c = warp_n * 64 + np * 16 + lcol;
            uint32_t addr = sbase + (uint32_t)((SM_BH + r * SSTRIDE + c) * 2);
            LDSM_X4_T(bf[np][0], bf[np][1], bf[np][2], bf[np][3], addr);
        }
#pragma unroll
        for (int mt = 0; mt < 2; mt++)
#pragma unroll
            for (int np = 0; np < 4; np++) {
                mma16816(acc[mt][np * 2 + 0], ah[mt], &bf[np][0]);
                mma16816(acc[mt][np * 2 + 1], ah[mt], &bf[np][2]);
                mma16816(acc[mt][np * 2 + 0], al[mt], &bf[np][0]);
                mma16816(acc[mt][np * 2 + 1], al[mt], &bf[np][2]);
            }
#pragma unroll
        for (int np = 0; np < 4; np++) {
            int r = ks * 16 + lrow;
            int c = warp_n * 64 + np * 16 + lcol;
            uint32_t addr = sbase + (uint32_t)((SM_BL + r * SSTRIDE + c) * 2);
            LDSM_X4_T(bf[np][0], bf[np][1], bf[np][2], bf[np][3], addr);
        }
#pragma unroll
        for (int mt = 0; mt < 2; mt++)
#pragma unroll
            for (int np = 0; np < 4; np++) {
                mma16816(acc[mt][np * 2 + 0], ah[mt], &bf[np][0]);
                mma16816(acc[mt][np * 2 + 1], ah[mt], &bf[np][2]);
            }
    }

    // --- epilogue: store y as fp16 (half2 per fragment pair) ----------------
    const int er0 = lane >> 2;            // 0..7
    const int ec = (lane & 3) * 2;
#pragma unroll
    for (int mt = 0; mt < 2; mt++) {
        int row0 = block_row + warp_m * 32 + mt * 16 + er0;
        int row1 = row0 + 8;
#pragma unroll
        for (int nt = 0; nt < 8; nt++) {
            int col = warp_n * 64 + nt * 8 + ec;
            if (row0 < M) {
                __half2 h = __floats2half2_rn(acc[mt][nt][0], acc[mt][nt][1]);
                *reinterpret_cast<__half2*>(g_yh + (size_t)row0 * FDIM + col) = h;
            }
            if (row1 < M) {
                __half2 h = __floats2half2_rn(acc[mt][nt][2], acc[mt][nt][3]);
                *reinterpret_cast<__half2*>(g_yh + (size_t)row1 * FDIM + col) = h;
            }
        }
    }
}

// ---------------------------------------------------------------------------
// CSR gather-aggregate, warp per node; y rows are fp16 (256 B/row),
// lane owns 4 consecutive halves (uint2 load), fp32 accumulation.
// acc = dinv[nd]*y[nd] + sum dinv[s]*y[s].
// FINAL==false: store fp32 acc to g_agg.
// FINAL==true : out = sigmoid(dinv[nd]*acc + b2); cols >= 123 forced to 0.7.
// ---------------------------------------------------------------------------
template <bool FINAL>
__global__ void __launch_bounds__(256)
agg_kernel(const float* __restrict__ b2, float* __restrict__ out, int n) {
    int nd = (int)((blockIdx.x * blockDim.x + threadIdx.x) >> 5);
    int lane = threadIdx.x & 31;
    if (nd >= n) return;
    const int c4 = lane * 4;

    int beg = g_off[nd];
    int end = g_off[nd + 1];
    float dself = g_dinv[nd];

    uint2 us = *reinterpret_cast<const uint2*>(g_yh + (size_t)nd * FDIM + c4);
    float2 s0f = __half22float2(*reinterpret_cast<__half2*>(&us.x));
    float2 s1f = __half22float2(*reinterpret_cast<__half2*>(&us.y));
    float4 acc = make_float4(s0f.x * dself, s0f.y * dself,
                             s1f.x * dself, s1f.y * dself);
    float4 acc2 = make_float4(0.f, 0.f, 0.f, 0.f);

    int j = beg;
    for (; j + 1 < end; j += 2) {
        int e0 = g_eidx[j];
        int e1 = g_eidx[j + 1];
        float d0 = g_dinv[e0];           // warp-uniform addr -> broadcast
        float d1 = g_dinv[e1];
        uint2 u0 = *reinterpret_cast<const uint2*>(g_yh + (size_t)e0 * FDIM + c4);
        uint2 u1 = *reinterpret_cast<const uint2*>(g_yh + (size_t)e1 * FDIM + c4);
        float2 a0 = __half22float2(*reinterpret_cast<__half2*>(&u0.x));
        float2 a1 = __half22float2(*reinterpret_cast<__half2*>(&u0.y));
        float2 b0 = __half22float2(*reinterpret_cast<__half2*>(&u1.x));
        float2 b1 = __half22float2(*reinterpret_cast<__half2*>(&u1.y));
        acc.x = fmaf(a0.x, d0, acc.x); acc.y = fmaf(a0.y, d0, acc.y);
        acc.z = fmaf(a1.x, d0, acc.z); acc.w = fmaf(a1.y, d0, acc.w);
        acc2.x = fmaf(b0.x, d1, acc2.x); acc2.y = fmaf(b0.y, d1, acc2.y);
        acc2.z = fmaf(b1.x, d1, acc2.z); acc2.w = fmaf(b1.y, d1, acc2.w);
    }
    if (j < end) {
        int e0 = g_eidx[j];
        float d0 = g_dinv[e0];
        uint2 u0 = *reinterpret_cast<const uint2*>(g_yh + (size_t)e0 * FDIM + c4);
        float2 a0 = __half22float2(*reinterpret_cast<__half2*>(&u0.x));
        float2 a1 = __half22float2(*reinterpret_cast<__half2*>(&u0.y));
        acc.x = fmaf(a0.x, d0, acc.x); acc.y = fmaf(a0.y, d0, acc.y);
        acc.z = fmaf(a1.x, d0, acc.z); acc.w = fmaf(a1.y, d0, acc.w);
    }
    acc.x += acc2.x; acc.y += acc2.y; acc.z += acc2.z; acc.w += acc2.w;

    if (!FINAL) {
        *reinterpret_cast<float4*>(g_agg + (size_t)nd * FDIM + c4) = acc;
    } else {
        float4 b = *reinterpret_cast<const float4*>(b2 + c4);
        float4 o;
        float t;
        t = fmaf(acc.x, dself, b.x); o.x = 1.0f / (1.0f + expf(-t));
        t = fmaf(acc.y, dself, b.y); o.y = 1.0f / (1.0f + expf(-t));
        t = fmaf(acc.z, dself, b.z); o.z = 1.0f / (1.0f + expf(-t));
        t = fmaf(acc.w, dself, b.w); o.w = 1.0f / (1.0f + expf(-t));
        if (c4 + 0 >= 123) o.x = 0.7f;
        if (c4 + 1 >= 123) o.y = 0.7f;
        if (c4 + 2 >= 123) o.z = 0.7f;
        if (c4 + 3 >= 123) o.w = 0.7f;
        *reinterpret_cast<float4*>(out + (size_t)nd * FDIM + c4) = o;
    }
}

// ---------------------------------------------------------------------------
extern "C" void kernel_launch(void* const* d_in, const int* in_sizes, int n_in,
                              void* d_out, int out_size) {
    const float* x  = (const float*)d_in[0];
    const void*  ei = d_in[1];
    const float* W1 = (const float*)d_in[2];
    const float* b1 = (const float*)d_in[3];
    const float* W2 = (const float*)d_in[4];
    const float* b2 = (const float*)d_in[5];
    float* out      = (float*)d_out;

    const int N = in_sizes[0] / FDIM;
    const int E = in_sizes[1] / 2;

    // one-time resources (persist across calls; graph-capture safe)
    static cudaStream_t s_side = nullptr;
    static cudaEvent_t ev_fork = nullptr, ev_join = nullptr;
    if (!s_side) {
        cudaStreamCreateWithFlags(&s_side, cudaStreamNonBlocking);
        cudaEventCreateWithFlags(&ev_fork, cudaEventDisableTiming);
        cudaEventCreateWithFlags(&ev_join, cudaEventDisableTiming);
        cudaFuncSetAttribute(gemm_mma_kernel<1>,
                             cudaFuncAttributeMaxDynamicSharedMemorySize, SM_BYTES);
        cudaFuncSetAttribute(gemm_mma_kernel<2>,
                             cudaFuncAttributeMaxDynamicSharedMemorySize, SM_BYTES);
    }

    const int gemm_blocks = (N + 127) / 128;
    const int agg_blocks  = (N + 7) / 8;
    const int eb = (E + 255) / 256;
    const int nb = (N + 1023) / 1024;   // scan blocks (<=128 for N<=131072)

    // ---- fork: CSR/degree build on side stream ----------------------------
    cudaEventRecord(ev_fork, 0);
    cudaStreamWaitEvent(s_side, ev_fork, 0);
    detect_init_kernel<<<1, 1, 0, s_side>>>();
    detect_zero_kernel<<<eb, 256, 0, s_side>>>(
        (const unsigned long long*)ei, E, (unsigned long long)N, N);
    cnt_accum_kernel<<<eb, 256, 0, s_side>>>(ei, E, N);
    scan1_kernel<<<nb, 1024, 0, s_side>>>(N);
    scan2_kernel<<<1, 128, 0, s_side>>>(nb, N);
    scan3_kernel<<<nb, 1024, 0, s_side>>>(N);
    place_kernel<<<eb, 256, 0, s_side>>>(ei, E, N);
    cudaEventRecord(ev_join, s_side);

    // ---- main stream: W prep + GEMM1 (independent of CSR) -----------------
    prep_w_kernel<0><<<32, 256>>>(W1);
    prep_w_kernel<1><<<32, 256>>>(W2);
    gemm_mma_kernel<1><<<gemm_blocks, 256, SM_BYTES>>>(x, nullptr, N);

    // ---- join, then aggregation + layer 2 ----------------------------------
    cudaStreamWaitEvent(0, ev_join, 0);
    agg_kernel<false><<<agg_blocks, 256>>>(nullptr, nullptr, N);
    gemm_mma_kernel<2><<<gemm_blocks, 256, SM_BYTES>>>(nullptr, b1, N);
    agg_kernel<true><<<agg_blocks, 256>>>(b2, out, N);
}

// round 14
// speedup vs baseline: 1.5761x; 1.1730x over previous
#include <cuda_runtime.h>
#include <cuda_fp16.h>
#include <cstdint>
#include <cmath>

#define NMAX 100000
#define EMAX 1600000
#define FDIM 128

// ---------------------------------------------------------------------------
// device globals (allocation-free scratch)
// ---------------------------------------------------------------------------
__device__ int   g_is64;
__device__ int   g_cnt[NMAX];
__device__ int   g_off[NMAX + 1];
__device__ int   g_cur[NMAX];
__device__ int   g_eidx[EMAX];
__device__ int   g_bsum[128];     // per-block partial sums (scan pass 1)
__device__ int   g_bbase[128];    // per-block exclusive bases (scan pass 2)
__device__ float g_dinv[NMAX];
__device__ __align__(16) __half g_yh[(size_t)NMAX * FDIM];  // y in fp16 (gather)
__device__ float g_agg[(size_t)NMAX * FDIM];                // fp32 aggregate
// W as fp16 pairs, plain [k][n/2] uint32 layout (128 x 64), 2 slots
__device__ __align__(16) uint32_t g_Wh[2][8192];

// ---------------------------------------------------------------------------
// warp-level MMA helpers (sm_80+ ISA: safe for plain sm_103 target)
// ---------------------------------------------------------------------------
__device__ __forceinline__ uint32_t smem_to_u32(const void* p) {
    uint32_t a;
    asm("{ .reg .u64 t; cvta.to.shared.u64 t, %1; cvt.u32.u64 %0, t; }"
        : "=r"(a) : "l"(p));
    return a;
}

#define LDSM_X4(r0, r1, r2, r3, addr) \
    asm volatile("ldmatrix.sync.aligned.m8n8.x4.shared.b16 {%0,%1,%2,%3}, [%4];" \
                 : "=r"(r0), "=r"(r1), "=r"(r2), "=r"(r3) : "r"(addr))
#define LDSM_X4_T(r0, r1, r2, r3, addr) \
    asm volatile("ldmatrix.sync.aligned.m8n8.x4.trans.shared.b16 {%0,%1,%2,%3}, [%4];" \
                 : "=r"(r0), "=r"(r1), "=r"(r2), "=r"(r3) : "r"(addr))

__device__ __forceinline__ void mma16816_f16(float* c, const uint32_t* a,
                                             const uint32_t* b) {
    asm volatile(
        "mma.sync.aligned.m16n8k16.row.col.f32.f16.f16.f32 "
        "{%0,%1,%2,%3}, {%4,%5,%6,%7}, {%8,%9}, {%0,%1,%2,%3};"
        : "+f"(c[0]), "+f"(c[1]), "+f"(c[2]), "+f"(c[3])
        : "r"(a[0]), "r"(a[1]), "r"(a[2]), "r"(a[3]), "r"(b[0]), "r"(b[1]));
}

// ---------------------------------------------------------------------------
// index dtype detection (+ fused g_cnt zeroing: E >> N so grid covers both)
// ---------------------------------------------------------------------------
__global__ void detect_init_kernel() { g_is64 = 1; }
__global__ void detect_zero_kernel(const unsigned long long* __restrict__ ei,
                                   int E, unsigned long long n64, int n) {
    int i = blockIdx.x * blockDim.x + threadIdx.x;
    if (i < n) g_cnt[i] = 0;
    if (i < E && ei[i] >= n64) g_is64 = 0;
}
__device__ __forceinline__ int load_idx(const void* ei, int i) {
    if (g_is64) return (int)((const long long*)ei)[i];
    return ((const int*)ei)[i];
}

// ---------------------------------------------------------------------------
// CSR build
// ---------------------------------------------------------------------------
__global__ void cnt_accum_kernel(const void* __restrict__ ei, int E, int n) {
    int e = blockIdx.x * blockDim.x + threadIdx.x;
    if (e < E) {
        int d = load_idx(ei, E + e);
        if ((unsigned)d < (unsigned)n) atomicAdd(&g_cnt[d], 1);
    }
}

// scan pass 1: per-block sums (1024 elems/block) + fused dinv
__global__ void __launch_bounds__(1024)
scan1_kernel(int n) {
    __shared__ int wsum[32];
    const int tid = threadIdx.x, lane = tid & 31, w = tid >> 5;
    int i = blockIdx.x * 1024 + tid;
    int v = (i < n) ? g_cnt[i] : 0;
    if (i < n) g_dinv[i] = rsqrtf((float)(v + 1));
    int s = v;
#pragma unroll
    for (int off = 16; off > 0; off >>= 1)
        s += __shfl_down_sync(0xffffffffu, s, off);
    if (lane == 0) wsum[w] = s;
    __syncthreads();
    if (w == 0) {
        int t = wsum[lane];
#pragma unroll
        for (int off = 16; off > 0; off >>= 1)
            t += __shfl_down_sync(0xffffffffu, t, off);
        if (lane == 0) g_bsum[blockIdx.x] = t;
    }
}

// scan pass 2: exclusive scan of <=128 block partials; writes g_off[n]=total
__global__ void __launch_bounds__(128)
scan2_kernel(int nb, int n) {
    __shared__ int ws[4];
    const int tid = threadIdx.x, lane = tid & 31, w = tid >> 5;
    int v = (tid < nb) ? g_bsum[tid] : 0;
    int s = v;
#pragma unroll
    for (int off = 1; off < 32; off <<= 1) {
        int t = __shfl_up_sync(0xffffffffu, s, off);
        if (lane >= off) s += t;
    }
    if (lane == 31) ws[w] = s;
    __syncthreads();
    int add = 0;
#pragma unroll
    for (int k = 0; k < 4; k++)
        if (k < w) add += ws[k];
    int incl = s + add;
    if (tid < nb) g_bbase[tid] = incl - v;   // exclusive base
    if (tid == nb - 1) g_off[n] = incl;      // grand total
}

// scan pass 3: block-local exclusive scan + base -> g_off/g_cur
__global__ void __launch_bounds__(1024)
scan3_kernel(int n) {
    __shared__ int wsum[32];
    const int tid = threadIdx.x, lane = tid & 31, w = tid >> 5;
    int i = blockIdx.x * 1024 + tid;
    int v = (i < n) ? g_cnt[i] : 0;
    int s = v;
#pragma unroll
    for (int off = 1; off < 32; off <<= 1) {
        int t = __shfl_up_sync(0xffffffffu, s, off);
        if (lane >= off) s += t;
    }
    if (lane == 31) wsum[w] = s;
    __syncthreads();
    if (w == 0) {
        int t = wsum[lane];
#pragma unroll
        for (int off = 1; off < 32; off <<= 1) {
            int u = __shfl_up_sync(0xffffffffu, t, off);
            if (lane >= off) t += u;
        }
        wsum[lane] = t;
    }
    __syncthreads();
    int excl = (s - v) + ((w > 0) ? wsum[w - 1] : 0) + g_bbase[blockIdx.x];
    if (i < n) {
        g_off[i] = excl;
        g_cur[i] = excl;
    }
}

__global__ void place_kernel(const void* __restrict__ ei, int E, int n) {
    int e = blockIdx.x * blockDim.x + threadIdx.x;
    if (e >= E) return;
    int s = load_idx(ei, e);
    int d = load_idx(ei, E + e);
    if ((unsigned)s >= (unsigned)n || (unsigned)d >= (unsigned)n) return;
    int p = atomicAdd(&g_cur[d], 1);
    g_eidx[p] = s;
}

// ---------------------------------------------------------------------------
// W prep: convert W (fp32 [K=128, N=128]) to fp16 pairs, [k][n/2] uint32,
// into slot SLOT.
// ---------------------------------------------------------------------------
template <int SLOT>
__global__ void __launch_bounds__(256)
prep_w_kernel(const float* __restrict__ W) {
    int j = blockIdx.x * blockDim.x + threadIdx.x;  // 0..8191
    if (j >= 8192) return;
    int k = j >> 6;
    int np = (j & 63) * 2;
    __half2 h = __floats2half2_rn(W[(size_t)k * FDIM + np],
                                  W[(size_t)k * FDIM + np + 1]);
    g_Wh[SLOT][j] = *reinterpret_cast<uint32_t*>(&h);
}

// ---------------------------------------------------------------------------
// HMMA GEMM (single fp16 term): y_row = act(A_row) @ W, y stored fp16,
// dinv deferred to agg. 128x128 tile/CTA, 8 warps (4x2), K=128,
// fp32 accumulators. 70KB smem -> 2 CTAs/SM.
// LAYER==1: A = X; LAYER==2: A = g_agg, act = relu(a*dinv[row] + b1[k]).
// ---------------------------------------------------------------------------
#define SSTRIDE 136   // fp16 elements per smem row (128 + 8 pad)
#define SM_A 0
#define SM_B (128 * SSTRIDE)
#define SM_ELEMS (2 * 128 * SSTRIDE)
#define SM_BYTES (SM_ELEMS * 2)

template <int LAYER>
__global__ void __launch_bounds__(256, 2)
gemm_mma_kernel(const float* __restrict__ X,
                const float* __restrict__ bin, int M) {
    extern __shared__ __align__(16) char smem_raw[];
    __half* sm = reinterpret_cast<__half*>(smem_raw);
    const uint32_t sbase = smem_to_u32(smem_raw);

    const int tid = threadIdx.x;
    const int wid = tid >> 5;
    const int lane = tid & 31;
    const int warp_m = wid & 3;       // 4 m-strips of 32 rows
    const int warp_n = wid >> 2;      // 2 n-strips of 64 cols
    const int block_row = blockIdx.x * 128;

    const float* Aptr = (LAYER == 1) ? X : (const float*)g_agg;
    const uint32_t* Bsrc = g_Wh[LAYER - 1];

    // --- load A (fp32), activation, convert fp16 into padded smem ----------
#pragma unroll
    for (int i = 0; i < 16; i++) {
        int f4 = tid + i * 256;           // 4096 float4s
        int row = f4 >> 5;
        int c4 = (f4 & 31) * 4;
        int grow = block_row + row;
        float4 av = make_float4(0.f, 0.f, 0.f, 0.f);
        if (grow < M) {
            av = *reinterpret_cast<const float4*>(Aptr + (size_t)grow * FDIM + c4);
            if (LAYER == 2) {
                float dv = g_dinv[grow];
                av.x = fmaxf(fmaf(av.x, dv, bin[c4 + 0]), 0.0f);
                av.y = fmaxf(fmaf(av.y, dv, bin[c4 + 1]), 0.0f);
                av.z = fmaxf(fmaf(av.z, dv, bin[c4 + 2]), 0.0f);
                av.w = fmaxf(fmaf(av.w, dv, bin[c4 + 3]), 0.0f);
            }
        }
        __half2 h0 = __floats2half2_rn(av.x, av.y);
        __half2 h1 = __floats2half2_rn(av.z, av.w);
        uint32_t* ap = reinterpret_cast<uint32_t*>(sm + SM_A + row * SSTRIDE + c4);
        ap[0] = *reinterpret_cast<uint32_t*>(&h0);
        ap[1] = *reinterpret_cast<uint32_t*>(&h1);
    }

    // --- copy W fp16 into padded smem (uint4 = 8 halves) --------------------
#pragma unroll
    for (int i = 0; i < 8; i++) {
        int u = tid + i * 256;            // 2048 uint4
        int row = u >> 4;
        int c8 = (u & 15) * 8;
        *reinterpret_cast<uint4*>(sm + SM_B + row * SSTRIDE + c8) =
            *(reinterpret_cast<const uint4*>(Bsrc) + u);
    }
    __syncthreads();

    // --- main MMA loop ------------------------------------------------------
    float acc[2][8][4];
#pragma unroll
    for (int mt = 0; mt < 2; mt++)
#pragma unroll
        for (int nt = 0; nt < 8; nt++)
#pragma unroll
            for (int q = 0; q < 4; q++) acc[mt][nt][q] = 0.0f;

    const int lrow = lane & 15;
    const int lcol = (lane >> 4) * 8;

#pragma unroll
    for (int ks = 0; ks < 8; ks++) {
        uint32_t ah[2][4], bf[4][4];
#pragma unroll
        for (int mt = 0; mt < 2; mt++) {
            int row = warp_m * 32 + mt * 16 + lrow;
            int col = ks * 16 + lcol;
            uint32_t addr = sbase + (uint32_t)((SM_A + row * SSTRIDE + col) * 2);
            LDSM_X4(ah[mt][0], ah[mt][1], ah[mt][2], ah[mt][3], addr);
        }
#pragma unroll
        for (int np = 0; np < 4; np++) {
            int r = ks * 16 + lrow;
            int c = warp_n * 64 + np * 16 + lcol;
            uint32_t addr = sbase + (uint32_t)((SM_B + r * SSTRIDE + c) * 2);
            LDSM_X4_T(bf[np][0], bf[np][1], bf[np][2], bf[np][3], addr);
        }
#pragma unroll
        for (int mt = 0; mt < 2; mt++)
#pragma unroll
            for (int np = 0; np < 4; np++) {
                mma16816_f16(acc[mt][np * 2 + 0], ah[mt], &bf[np][0]);
                mma16816_f16(acc[mt][np * 2 + 1], ah[mt], &bf[np][2]);
            }
    }

    // --- epilogue: store y as fp16 (half2 per fragment pair) ----------------
    const int er0 = lane >> 2;            // 0..7
    const int ec = (lane & 3) * 2;
#pragma unroll
    for (int mt = 0; mt < 2; mt++) {
        int row0 = block_row + warp_m * 32 + mt * 16 + er0;
        int row1 = row0 + 8;
#pragma unroll
        for (int nt = 0; nt < 8; nt++) {
            int col = warp_n * 64 + nt * 8 + ec;
            if (row0 < M) {
                __half2 h = __floats2half2_rn(acc[mt][nt][0], acc[mt][nt][1]);
                *reinterpret_cast<__half2*>(g_yh + (size_t)row0 * FDIM + col) = h;
            }
            if (row1 < M) {
                __half2 h = __floats2half2_rn(acc[mt][nt][2], acc[mt][nt][3]);
                *reinterpret_cast<__half2*>(g_yh + (size_t)row1 * FDIM + col) = h;
            }
        }
    }
}

// ---------------------------------------------------------------------------
// CSR gather-aggregate, warp per node; y rows are fp16 (256 B/row),
// lane owns 4 consecutive halves (uint2 load), fp32 accumulation.
// acc = dinv[nd]*y[nd] + sum dinv[s]*y[s].
// FINAL==false: store fp32 acc to g_agg.
// FINAL==true : out = sigmoid(dinv[nd]*acc + b2); cols >= 123 forced to 0.7.
// ---------------------------------------------------------------------------
template <bool FINAL>
__global__ void __launch_bounds__(256)
agg_kernel(const float* __restrict__ b2, float* __restrict__ out, int n) {
    int nd = (int)((blockIdx.x * blockDim.x + threadIdx.x) >> 5);
    int lane = threadIdx.x & 31;
    if (nd >= n) return;
    const int c4 = lane * 4;

    int beg = g_off[nd];
    int end = g_off[nd + 1];
    float dself = g_dinv[nd];

    uint2 us = *reinterpret_cast<const uint2*>(g_yh + (size_t)nd * FDIM + c4);
    float2 s0f = __half22float2(*reinterpret_cast<__half2*>(&us.x));
    float2 s1f = __half22float2(*reinterpret_cast<__half2*>(&us.y));
    float4 acc = make_float4(s0f.x * dself, s0f.y * dself,
                             s1f.x * dself, s1f.y * dself);
    float4 acc2 = make_float4(0.f, 0.f, 0.f, 0.f);

    int j = beg;
    for (; j + 1 < end; j += 2) {
        int e0 = g_eidx[j];
        int e1 = g_eidx[j + 1];
        float d0 = g_dinv[e0];           // warp-uniform addr -> broadcast
        float d1 = g_dinv[e1];
        uint2 u0 = *reinterpret_cast<const uint2*>(g_yh + (size_t)e0 * FDIM + c4);
        uint2 u1 = *reinterpret_cast<const uint2*>(g_yh + (size_t)e1 * FDIM + c4);
        float2 a0 = __half22float2(*reinterpret_cast<__half2*>(&u0.x));
        float2 a1 = __half22float2(*reinterpret_cast<__half2*>(&u0.y));
        float2 b0 = __half22float2(*reinterpret_cast<__half2*>(&u1.x));
        float2 b1 = __half22float2(*reinterpret_cast<__half2*>(&u1.y));
        acc.x = fmaf(a0.x, d0, acc.x); acc.y = fmaf(a0.y, d0, acc.y);
        acc.z = fmaf(a1.x, d0, acc.z); acc.w = fmaf(a1.y, d0, acc.w);
        acc2.x = fmaf(b0.x, d1, acc2.x); acc2.y = fmaf(b0.y, d1, acc2.y);
        acc2.z = fmaf(b1.x, d1, acc2.z); acc2.w = fmaf(b1.y, d1, acc2.w);
    }
    if (j < end) {
        int e0 = g_eidx[j];
        float d0 = g_dinv[e0];
        uint2 u0 = *reinterpret_cast<const uint2*>(g_yh + (size_t)e0 * FDIM + c4);
        float2 a0 = __half22float2(*reinterpret_cast<__half2*>(&u0.x));
        float2 a1 = __half22float2(*reinterpret_cast<__half2*>(&u0.y));
        acc.x = fmaf(a0.x, d0, acc.x); acc.y = fmaf(a0.y, d0, acc.y);
        acc.z = fmaf(a1.x, d0, acc.z); acc.w = fmaf(a1.y, d0, acc.w);
    }
    acc.x += acc2.x; acc.y += acc2.y; acc.z += acc2.z; acc.w += acc2.w;

    if (!FINAL) {
        *reinterpret_cast<float4*>(g_agg + (size_t)nd * FDIM + c4) = acc;
    } else {
        float4 b = *reinterpret_cast<const float4*>(b2 + c4);
        float4 o;
        float t;
        t = fmaf(acc.x, dself, b.x); o.x = 1.0f / (1.0f + expf(-t));
        t = fmaf(acc.y, dself, b.y); o.y = 1.0f / (1.0f + expf(-t));
        t = fmaf(acc.z, dself, b.z); o.z = 1.0f / (1.0f + expf(-t));
        t = fmaf(acc.w, dself, b.w); o.w = 1.0f / (1.0f + expf(-t));
        if (c4 + 0 >= 123) o.x = 0.7f;
        if (c4 + 1 >= 123) o.y = 0.7f;
        if (c4 + 2 >= 123) o.z = 0.7f;
        if (c4 + 3 >= 123) o.w = 0.7f;
        *reinterpret_cast<float4*>(out + (size_t)nd * FDIM + c4) = o;
    }
}

// ---------------------------------------------------------------------------
extern "C" void kernel_launch(void* const* d_in, const int* in_sizes, int n_in,
                              void* d_out, int out_size) {
    const float* x  = (const float*)d_in[0];
    const void*  ei = d_in[1];
    const float* W1 = (const float*)d_in[2];
    const float* b1 = (const float*)d_in[3];
    const float* W2 = (const float*)d_in[4];
    const float* b2 = (const float*)d_in[5];
    float* out      = (float*)d_out;

    const int N = in_sizes[0] / FDIM;
    const int E = in_sizes[1] / 2;

    // one-time resources (persist across calls; graph-capture safe)
    static cudaStream_t s_side = nullptr;
    static cudaEvent_t ev_fork = nullptr, ev_join = nullptr;
    if (!s_side) {
        cudaStreamCreateWithFlags(&s_side, cudaStreamNonBlocking);
        cudaEventCreateWithFlags(&ev_fork, cudaEventDisableTiming);
        cudaEventCreateWithFlags(&ev_join, cudaEventDisableTiming);
        cudaFuncSetAttribute(gemm_mma_kernel<1>,
                             cudaFuncAttributeMaxDynamicSharedMemorySize, SM_BYTES);
        cudaFuncSetAttribute(gemm_mma_kernel<2>,
                             cudaFuncAttributeMaxDynamicSharedMemorySize, SM_BYTES);
    }

    const int gemm_blocks = (N + 127) / 128;
    const int agg_blocks  = (N + 7) / 8;
    const int eb = (E + 255) / 256;
    const int nb = (N + 1023) / 1024;   // scan blocks (<=128 for N<=131072)

    // ---- fork: CSR/degree build on side stream ----------------------------
    cudaEventRecord(ev_fork, 0);
    cudaStreamWaitEvent(s_side, ev_fork, 0);
    detect_init_kernel<<<1, 1, 0, s_side>>>();
    detect_zero_kernel<<<eb, 256, 0, s_side>>>(
        (const unsigned long long*)ei, E, (unsigned long long)N, N);
    cnt_accum_kernel<<<eb, 256, 0, s_side>>>(ei, E, N);
    scan1_kernel<<<nb, 1024, 0, s_side>>>(N);
    scan2_kernel<<<1, 128, 0, s_side>>>(nb, N);
    scan3_kernel<<<nb, 1024, 0, s_side>>>(N);
    place_kernel<<<eb, 256, 0, s_side>>>(ei, E, N);
    cudaEventRecord(ev_join, s_side);

    // ---- main stream: W prep + GEMM1 (independent of CSR) -----------------
    prep_w_kernel<0><<<32, 256>>>(W1);
    prep_w_kernel<1><<<32, 256>>>(W2);
    gemm_mma_kernel<1><<<gemm_blocks, 256, SM_BYTES>>>(x, nullptr, N);

    // ---- join, then aggregation + layer 2 ----------------------------------
    cudaStreamWaitEvent(0, ev_join, 0);
    agg_kernel<false><<<agg_blocks, 256>>>(nullptr, nullptr, N);
    gemm_mma_kernel<2><<<gemm_blocks, 256, SM_BYTES>>>(nullptr, b1, N);
    agg_kernel<true><<<agg_blocks, 256>>>(b2, out, N);
}

// round 17
// speedup vs baseline: 1.6793x; 1.0654x over previous
#include <cuda_runtime.h>
#include <cuda_fp16.h>
#include <cstdint>
#include <cmath>

#define NMAX 100000
#define EMAX 1600000
#define FDIM 128

// ---------------------------------------------------------------------------
// device globals (allocation-free scratch)
// ---------------------------------------------------------------------------
__device__ int   g_is64;
__device__ int   g_cnt[NMAX];
__device__ int   g_off[NMAX + 1];
__device__ int   g_cur[NMAX];
__device__ int   g_eidx[EMAX];
__device__ int   g_bsum[128];     // per-block partial sums (scan pass 1)
__device__ int   g_bbase[128];    // per-block exclusive bases (scan pass 2)
__device__ float g_dinv[NMAX];
__device__ __align__(16) __half g_yh[(size_t)NMAX * FDIM];   // y (fp16, gather)
__device__ __align__(16) __half g_aggh[(size_t)NMAX * FDIM]; // layer-1 agg (fp16)
// W as fp16 pairs, plain [k][n/2] uint32 layout (128 x 64), 2 slots
__device__ __align__(16) uint32_t g_Wh[2][8192];

// ---------------------------------------------------------------------------
// warp-level MMA helpers (sm_80+ ISA: safe for plain sm_103 target)
// ---------------------------------------------------------------------------
__device__ __forceinline__ uint32_t smem_to_u32(const void* p) {
    uint32_t a;
    asm("{ .reg .u64 t; cvta.to.shared.u64 t, %1; cvt.u32.u64 %0, t; }"
        : "=r"(a) : "l"(p));
    return a;
}

#define LDSM_X4(r0, r1, r2, r3, addr) \
    asm volatile("ldmatrix.sync.aligned.m8n8.x4.shared.b16 {%0,%1,%2,%3}, [%4];" \
                 : "=r"(r0), "=r"(r1), "=r"(r2), "=r"(r3) : "r"(addr))
#define LDSM_X4_T(r0, r1, r2, r3, addr) \
    asm volatile("ldmatrix.sync.aligned.m8n8.x4.trans.shared.b16 {%0,%1,%2,%3}, [%4];" \
                 : "=r"(r0), "=r"(r1), "=r"(r2), "=r"(r3) : "r"(addr))

__device__ __forceinline__ void mma16816_f16(float* c, const uint32_t* a,
                                             const uint32_t* b) {
    asm volatile(
        "mma.sync.aligned.m16n8k16.row.col.f32.f16.f16.f32 "
        "{%0,%1,%2,%3}, {%4,%5,%6,%7}, {%8,%9}, {%0,%1,%2,%3};"
        : "+f"(c[0]), "+f"(c[1]), "+f"(c[2]), "+f"(c[3])
        : "r"(a[0]), "r"(a[1]), "r"(a[2]), "r"(a[3]), "r"(b[0]), "r"(b[1]));
}

// ---------------------------------------------------------------------------
// index dtype detection: single block, first min(E,4096) words.
// int32 data read as u64 has a random high word (>=N w.p. ~1 per word).
// ---------------------------------------------------------------------------
__global__ void detect_kernel(const unsigned long long* __restrict__ ei,
                              int E, unsigned long long n) {
    __shared__ int found;
    if (threadIdx.x == 0) found = 0;
    __syncthreads();
    int K = (E < 4096) ? E : 4096;
    for (int i = threadIdx.x; i < K; i += 256)
        if (ei[i] >= n) found = 1;
    __syncthreads();
    if (threadIdx.x == 0) g_is64 = found ? 0 : 1;
}
__device__ __forceinline__ int load_idx(const void* ei, int i) {
    if (g_is64) return (int)((const long long*)ei)[i];
    return ((const int*)ei)[i];
}

__global__ void zero_cnt_kernel(int n) {
    int i = blockIdx.x * blockDim.x + threadIdx.x;
    if (i < n) g_cnt[i] = 0;
}

// ---------------------------------------------------------------------------
// CSR build (4 edges/thread for MLP)
// ---------------------------------------------------------------------------
__global__ void cnt_accum_kernel(const void* __restrict__ ei, int E, int n) {
    int base = (blockIdx.x * blockDim.x + threadIdx.x) * 4;
    int d[4];
#pragma unroll
    for (int k = 0; k < 4; k++)
        d[k] = (base + k < E) ? load_idx(ei, E + base + k) : -1;
#pragma unroll
    for (int k = 0; k < 4; k++)
        if ((unsigned)d[k] < (unsigned)n) atomicAdd(&g_cnt[d[k]], 1);
}

// scan pass 1: per-block sums (1024 elems/block) + fused dinv
__global__ void __launch_bounds__(1024)
scan1_kernel(int n) {
    __shared__ int wsum[32];
    const int tid = threadIdx.x, lane = tid & 31, w = tid >> 5;
    int i = blockIdx.x * 1024 + tid;
    int v = (i < n) ? g_cnt[i] : 0;
    if (i < n) g_dinv[i] = rsqrtf((float)(v + 1));
    int s = v;
#pragma unroll
    for (int off = 16; off > 0; off >>= 1)
        s += __shfl_down_sync(0xffffffffu, s, off);
    if (lane == 0) wsum[w] = s;
    __syncthreads();
    if (w == 0) {
        int t = wsum[lane];
#pragma unroll
        for (int off = 16; off > 0; off >>= 1)
            t += __shfl_down_sync(0xffffffffu, t, off);
        if (lane == 0) g_bsum[blockIdx.x] = t;
    }
}

// scan pass 2: exclusive scan of <=128 block partials; writes g_off[n]=total
__global__ void __launch_bounds__(128)
scan2_kernel(int nb, int n) {
    __shared__ int ws[4];
    const int tid = threadIdx.x, lane = tid & 31, w = tid >> 5;
    int v = (tid < nb) ? g_bsum[tid] : 0;
    int s = v;
#pragma unroll
    for (int off = 1; off < 32; off <<= 1) {
        int t = __shfl_up_sync(0xffffffffu, s, off);
        if (lane >= off) s += t;
    }
    if (lane == 31) ws[w] = s;
    __syncthreads();
    int add = 0;
#pragma unroll
    for (int k = 0; k < 4; k++)
        if (k < w) add += ws[k];
    int incl = s + add;
    if (tid < nb) g_bbase[tid] = incl - v;   // exclusive base
    if (tid == nb - 1) g_off[n] = incl;      // grand total
}

// scan pass 3: block-local exclusive scan + base -> g_off/g_cur
__global__ void __launch_bounds__(1024)
scan3_kernel(int n) {
    __shared__ int wsum[32];
    const int tid = threadIdx.x, lane = tid & 31, w = tid >> 5;
    int i = blockIdx.x * 1024 + tid;
    int v = (i < n) ? g_cnt[i] : 0;
    int s = v;
#pragma unroll
    for (int off = 1; off < 32; off <<= 1) {
        int t = __shfl_up_sync(0xffffffffu, s, off);
        if (lane >= off) s += t;
    }
    if (lane == 31) wsum[w] = s;
    __syncthreads();
    if (w == 0) {
        int t = wsum[lane];
#pragma unroll
        for (int off = 1; off < 32; off <<= 1) {
            int u = __shfl_up_sync(0xffffffffu, t, off);
            if (lane >= off) t += u;
        }
        wsum[lane] = t;
    }
    __syncthreads();
    int excl = (s - v) + ((w > 0) ? wsum[w - 1] : 0) + g_bbase[blockIdx.x];
    if (i < n) {
        g_off[i] = excl;
        g_cur[i] = excl;
    }
}

__global__ void place_kernel(const void* __restrict__ ei, int E, int n) {
    int base = (blockIdx.x * blockDim.x + threadIdx.x) * 4;
    int s[4], d[4];
#pragma unroll
    for (int k = 0; k < 4; k++) {
        s[k] = (base + k < E) ? load_idx(ei, base + k) : -1;
        d[k] = (base + k < E) ? load_idx(ei, E + base + k) : -1;
    }
#pragma unroll
    for (int k = 0; k < 4; k++) {
        if ((unsigned)s[k] < (unsigned)n && (unsigned)d[k] < (unsigned)n) {
            int p = atomicAdd(&g_cur[d[k]], 1);
            g_eidx[p] = s[k];
        }
    }
}

// ---------------------------------------------------------------------------
// W prep: convert both W matrices (fp32 [K=128, N=128]) to fp16 pairs,
// [k][n/2] uint32 layout, slots 0/1. One kernel, 16384 items.
// ---------------------------------------------------------------------------
__global__ void __launch_bounds__(256)
prep_w_kernel(const float* __restrict__ W1, const float* __restrict__ W2) {
    int g = blockIdx.x * blockDim.x + threadIdx.x;  // 0..16383
    if (g >= 16384) return;
    int slot = g >> 13;
    int j = g & 8191;
    const float* W = slot ? W2 : W1;
    int k = j >> 6;
    int np = (j & 63) * 2;
    __half2 h = __floats2half2_rn(W[(size_t)k * FDIM + np],
                                  W[(size_t)k * FDIM + np + 1]);
    g_Wh[slot][j] = *reinterpret_cast<uint32_t*>(&h);
}

// ---------------------------------------------------------------------------
// HMMA GEMM (single fp16 term): y_row = act(A_row) @ W, y stored fp16,
// dinv deferred to agg. 128x128 tile/CTA, 8 warps (4x2), K=128,
// fp32 accumulators. 70KB smem -> 2 CTAs/SM.
// LAYER==1: A = X (fp32); LAYER==2: A = g_aggh (fp16),
//           act = relu(a*dinv[row] + b1[k]).
// ---------------------------------------------------------------------------
#define SSTRIDE 136   // fp16 elements per smem row (128 + 8 pad)
#define SM_A 0
#define SM_B (128 * SSTRIDE)
#define SM_ELEMS (2 * 128 * SSTRIDE)
#define SM_BYTES (SM_ELEMS * 2)

template <int LAYER>
__global__ void __launch_bounds__(256, 2)
gemm_mma_kernel(const float* __restrict__ X,
                const float* __restrict__ bin, int M) {
    extern __shared__ __align__(16) char smem_raw[];
    __half* sm = reinterpret_cast<__half*>(smem_raw);
    const uint32_t sbase = smem_to_u32(smem_raw);

    const int tid = threadIdx.x;
    const int wid = tid >> 5;
    const int lane = tid & 31;
    const int warp_m = wid & 3;       // 4 m-strips of 32 rows
    const int warp_n = wid >> 2;      // 2 n-strips of 64 cols
    const int block_row = blockIdx.x * 128;

    const uint32_t* Bsrc = g_Wh[LAYER - 1];

    // --- load A + activation + fp16 into padded smem ------------------------
    if (LAYER == 1) {
#pragma unroll
        for (int i = 0; i < 16; i++) {
            int f4 = tid + i * 256;           // 4096 float4s
            int row = f4 >> 5;
            int c4 = (f4 & 31) * 4;
            int grow = block_row + row;
            float4 av = make_float4(0.f, 0.f, 0.f, 0.f);
            if (grow < M)
                av = *reinterpret_cast<const float4*>(X + (size_t)grow * FDIM + c4);
            __half2 h0 = __floats2half2_rn(av.x, av.y);
            __half2 h1 = __floats2half2_rn(av.z, av.w);
            uint32_t* ap = reinterpret_cast<uint32_t*>(sm + SM_A + row * SSTRIDE + c4);
            ap[0] = *reinterpret_cast<uint32_t*>(&h0);
            ap[1] = *reinterpret_cast<uint32_t*>(&h1);
        }
    } else {
        // fp16 agg source: 2048 uint4 (8 halves each)
#pragma unroll
        for (int i = 0; i < 8; i++) {
            int u = tid + i * 256;
            int row = u >> 4;
            int c8 = (u & 15) * 8;
            int grow = block_row + row;
            uint4 v = make_uint4(0, 0, 0, 0);
            float dv = 0.0f;
            if (grow < M) {
                v = *reinterpret_cast<const uint4*>(g_aggh + (size_t)grow * FDIM + c8);
                dv = g_dinv[grow];
            }
            float2 f0 = __half22float2(*reinterpret_cast<__half2*>(&v.x));
            float2 f1 = __half22float2(*reinterpret_cast<__half2*>(&v.y));
            float2 f2 = __half22float2(*reinterpret_cast<__half2*>(&v.z));
            float2 f3 = __half22float2(*reinterpret_cast<__half2*>(&v.w));
            float r0 = fmaxf(fmaf(f0.x, dv, bin[c8 + 0]), 0.0f);
            float r1 = fmaxf(fmaf(f0.y, dv, bin[c8 + 1]), 0.0f);
            float r2 = fmaxf(fmaf(f1.x, dv, bin[c8 + 2]), 0.0f);
            float r3 = fmaxf(fmaf(f1.y, dv, bin[c8 + 3]), 0.0f);
            float r4 = fmaxf(fmaf(f2.x, dv, bin[c8 + 4]), 0.0f);
            float r5 = fmaxf(fmaf(f2.y, dv, bin[c8 + 5]), 0.0f);
            float r6 = fmaxf(fmaf(f3.x, dv, bin[c8 + 6]), 0.0f);
            float r7 = fmaxf(fmaf(f3.y, dv, bin[c8 + 7]), 0.0f);
            __half2 h0 = __floats2half2_rn(r0, r1);
            __half2 h1 = __floats2half2_rn(r2, r3);
            __half2 h2 = __floats2half2_rn(r4, r5);
            __half2 h3 = __floats2half2_rn(r6, r7);
            uint4 pk;
            pk.x = *reinterpret_cast<uint32_t*>(&h0);
            pk.y = *reinterpret_cast<uint32_t*>(&h1);
            pk.z = *reinterpret_cast<uint32_t*>(&h2);
            pk.w = *reinterpret_cast<uint32_t*>(&h3);
            *reinterpret_cast<uint4*>(sm + SM_A + row * SSTRIDE + c8) = pk;
        }
    }

    // --- copy W fp16 into padded smem (uint4 = 8 halves) --------------------
#pragma unroll
    for (int i = 0; i < 8; i++) {
        int u = tid + i * 256;            // 2048 uint4
        int row = u >> 4;
        int c8 = (u & 15) * 8;
        *reinterpret_cast<uint4*>(sm + SM_B + row * SSTRIDE + c8) =
            *(reinterpret_cast<const uint4*>(Bsrc) + u);
    }
    __syncthreads();

    // --- main MMA loop ------------------------------------------------------
    float acc[2][8][4];
#pragma unroll
    for (int mt = 0; mt < 2; mt++)
#pragma unroll
        for (int nt = 0; nt < 8; nt++)
#pragma unroll
            for (int q = 0; q < 4; q++) acc[mt][nt][q] = 0.0f;

    const int lrow = lane & 15;
    const int lcol = (lane >> 4) * 8;

#pragma unroll
    for (int ks = 0; ks < 8; ks++) {
        uint32_t ah[2][4], bf[4][4];
#pragma unroll
        for (int mt = 0; mt < 2; mt++) {
            int row = warp_m * 32 + mt * 16 + lrow;
            int col = ks * 16 + lcol;
            uint32_t addr = sbase + (uint32_t)((SM_A + row * SSTRIDE + col) * 2);
            LDSM_X4(ah[mt][0], ah[mt][1], ah[mt][2], ah[mt][3], addr);
        }
#pragma unroll
        for (int np = 0; np < 4; np++) {
            int r = ks * 16 + lrow;
            int c = warp_n * 64 + np * 16 + lcol;
            uint32_t addr = sbase + (uint32_t)((SM_B + r * SSTRIDE + c) * 2);
            LDSM_X4_T(bf[np][0], bf[np][1], bf[np][2], bf[np][3], addr);
        }
#pragma unroll
        for (int mt = 0; mt < 2; mt++)
#pragma unroll
            for (int np = 0; np < 4; np++) {
                mma16816_f16(acc[mt][np * 2 + 0], ah[mt], &bf[np][0]);
                mma16816_f16(acc[mt][np * 2 + 1], ah[mt], &bf[np][2]);
            }
    }

    // --- epilogue: store y as fp16 (half2 per fragment pair) ----------------
    const int er0 = lane >> 2;            // 0..7
    const int ec = (lane & 3) * 2;
#pragma unroll
    for (int mt = 0; mt < 2; mt++) {
        int row0 = block_row + warp_m * 32 + mt * 16 + er0;
        int row1 = row0 + 8;
#pragma unroll
        for (int nt = 0; nt < 8; nt++) {
            int col = warp_n * 64 + nt * 8 + ec;
            if (row0 < M) {
                __half2 h = __floats2half2_rn(acc[mt][nt][0], acc[mt][nt][1]);
                *reinterpret_cast<__half2*>(g_yh + (size_t)row0 * FDIM + col) = h;
            }
            if (row1 < M) {
                __half2 h = __floats2half2_rn(acc[mt][nt][2], acc[mt][nt][3]);
                *reinterpret_cast<__half2*>(g_yh + (size_t)row1 * FDIM + col) = h;
            }
        }
    }
}

// ---------------------------------------------------------------------------
// CSR gather-aggregate, warp per node, HALF-WARP per edge:
// lane = half*16 + hl; each lane covers 8 cols (uint4 of g_yh), the two
// half-warps interleave over the edge list (2 rows in flight per warp,
// 4 with the inner 2-way unroll). Combine via shfl_xor(16).
// acc = dinv[nd]*y[nd] + sum dinv[s]*y[s].
// FINAL==false: store fp16 acc to g_aggh.
// FINAL==true : out = sigmoid(dinv[nd]*acc + b2); cols >= 123 forced to 0.7.
// ---------------------------------------------------------------------------
template <bool FINAL>
__global__ void __launch_bounds__(256)
agg_kernel(const float* __restrict__ b2, float* __restrict__ out, int n) {
    int nd = (int)((blockIdx.x * blockDim.x + threadIdx.x) >> 5);
    int lane = threadIdx.x & 31;
    if (nd >= n) return;
    const int half = lane >> 4;
    const int c8 = (lane & 15) * 8;

    int beg = g_off[nd];
    int end = g_off[nd + 1];
    float dself = g_dinv[nd];

    float acc[8], acc2[8];
#pragma unroll
    for (int i = 0; i < 8; i++) { acc[i] = 0.f; acc2[i] = 0.f; }

    if (half == 0) {
        uint4 u = *reinterpret_cast<const uint4*>(g_yh + (size_t)nd * FDIM + c8);
        float2 f0 = __half22float2(*reinterpret_cast<__half2*>(&u.x));
        float2 f1 = __half22float2(*reinterpret_cast<__half2*>(&u.y));
        float2 f2 = __half22float2(*reinterpret_cast<__half2*>(&u.z));
        float2 f3 = __half22float2(*reinterpret_cast<__half2*>(&u.w));
        acc[0] = f0.x * dself; acc[1] = f0.y * dself;
        acc[2] = f1.x * dself; acc[3] = f1.y * dself;
        acc[4] = f2.x * dself; acc[5] = f2.y * dself;
        acc[6] = f3.x * dself; acc[7] = f3.y * dself;
    }

    int j = beg + half;
    for (; j + 2 < end; j += 4) {          // 2 rows in flight per half-warp
        int e0 = g_eidx[j];
        int e1 = g_eidx[j + 2];
        float d0 = g_dinv[e0];
        float d1 = g_dinv[e1];
        uint4 u0 = *reinterpret_cast<const uint4*>(g_yh + (size_t)e0 * FDIM + c8);
        uint4 u1 = *reinterpret_cast<const uint4*>(g_yh + (size_t)e1 * FDIM + c8);
        float2 a0 = __half22float2(*reinterpret_cast<__half2*>(&u0.x));
        float2 a1 = __half22float2(*reinterpret_cast<__half2*>(&u0.y));
        float2 a2 = __half22float2(*reinterpret_cast<__half2*>(&u0.z));
        float2 a3 = __half22float2(*reinterpret_cast<__half2*>(&u0.w));
        acc[0] = fmaf(a0.x, d0, acc[0]); acc[1] = fmaf(a0.y, d0, acc[1]);
        acc[2] = fmaf(a1.x, d0, acc[2]); acc[3] = fmaf(a1.y, d0, acc[3]);
        acc[4] = fmaf(a2.x, d0, acc[4]); acc[5] = fmaf(a2.y, d0, acc[5]);
        acc[6] = fmaf(a3.x, d0, acc[6]); acc[7] = fmaf(a3.y, d0, acc[7]);
        float2 b0f = __half22float2(*reinterpret_cast<__half2*>(&u1.x));
        float2 b1f = __half22float2(*reinterpret_cast<__half2*>(&u1.y));
        float2 b2f = __half22float2(*reinterpret_cast<__half2*>(&u1.z));
        float2 b3f = __half22float2(*reinterpret_cast<__half2*>(&u1.w));
        acc2[0] = fmaf(b0f.x, d1, acc2[0]); acc2[1] = fmaf(b0f.y, d1, acc2[1]);
        acc2[2] = fmaf(b1f.x, d1, acc2[2]); acc2[3] = fmaf(b1f.y, d1, acc2[3]);
        acc2[4] = fmaf(b2f.x, d1, acc2[4]); acc2[5] = fmaf(b2f.y, d1, acc2[5]);
        acc2[6] = fmaf(b3f.x, d1, acc2[6]); acc2[7] = fmaf(b3f.y, d1, acc2[7]);
    }
    if (j < end) {
        int e0 = g_eidx[j];
        float d0 = g_dinv[e0];
        uint4 u0 = *reinterpret_cast<const uint4*>(g_yh + (size_t)e0 * FDIM + c8);
        float2 a0 = __half22float2(*reinterpret_cast<__half2*>(&u0.x));
        float2 a1 = __half22float2(*reinterpret_cast<__half2*>(&u0.y));
        float2 a2 = __half22float2(*reinterpret_cast<__half2*>(&u0.z));
        float2 a3 = __half22float2(*reinterpret_cast<__half2*>(&u0.w));
        acc[0] = fmaf(a0.x, d0, acc[0]); acc[1] = fmaf(a0.y, d0, acc[1]);
        acc[2] = fmaf(a1.x, d0, acc[2]); acc[3] = fmaf(a1.y, d0, acc[3]);
        acc[4] = fmaf(a2.x, d0, acc[4]); acc[5] = fmaf(a2.y, d0, acc[5]);
        acc[6] = fmaf(a3.x, d0, acc[6]); acc[7] = fmaf(a3.y, d0, acc[7]);
    }
#pragma unroll
    for (int i = 0; i < 8; i++) acc[i] += acc2[i];

    __syncwarp();
#pragma unroll
    for (int i = 0; i < 8; i++)
        acc[i] += __shfl_xor_sync(0xffffffffu, acc[i], 16);

    if (half != 0) return;

    if (!FINAL) {
        __half2 h0 = __floats2half2_rn(acc[0], acc[1]);
        __half2 h1 = __floats2half2_rn(acc[2], acc[3]);
        __half2 h2 = __floats2half2_rn(acc[4], acc[5]);
        __half2 h3 = __floats2half2_rn(acc[6], acc[7]);
        uint4 pk;
        pk.x = *reinterpret_cast<uint32_t*>(&h0);
        pk.y = *reinterpret_cast<uint32_t*>(&h1);
        pk.z = *reinterpret_cast<uint32_t*>(&h2);
        pk.w = *reinterpret_cast<uint32_t*>(&h3);
        *reinterpret_cast<uint4*>(g_aggh + (size_t)nd * FDIM + c8) = pk;
    } else {
        float o[8];
#pragma unroll
        for (int i = 0; i < 8; i++) {
            float t = fmaf(acc[i], dself, b2[c8 + i]);
            o[i] = 1.0f / (1.0f + expf(-t));
            if (c8 + i >= 123) o[i] = 0.7f;
        }
        float4 v0 = make_float4(o[0], o[1], o[2], o[3]);
        float4 v1 = make_float4(o[4], o[5], o[6], o[7]);
        *reinterpret_cast<float4*>(out + (size_t)nd * FDIM + c8) = v0;
        *reinterpret_cast<float4*>(out + (size_t)nd * FDIM + c8 + 4) = v1;
    }
}

// ---------------------------------------------------------------------------
extern "C" void kernel_launch(void* const* d_in, const int* in_sizes, int n_in,
                              void* d_out, int out_size) {
    const float* x  = (const float*)d_in[0];
    const void*  ei = d_in[1];
    const float* W1 = (const float*)d_in[2];
    const float* b1 = (const float*)d_in[3];
    const float* W2 = (const float*)d_in[4];
    const float* b2 = (const float*)d_in[5];
    float* out      = (float*)d_out;

    const int N = in_sizes[0] / FDIM;
    const int E = in_sizes[1] / 2;

    // one-time resources (persist across calls; graph-capture safe)
    static cudaStream_t s_side = nullptr;
    static cudaEvent_t ev_fork = nullptr, ev_join = nullptr;
    if (!s_side) {
        cudaStreamCreateWithFlags(&s_side, cudaStreamNonBlocking);
        cudaEventCreateWithFlags(&ev_fork, cudaEventDisableTiming);
        cudaEventCreateWithFlags(&ev_join, cudaEventDisableTiming);
        cudaFuncSetAttribute(gemm_mma_kernel<1>,
                             cudaFuncAttributeMaxDynamicSharedMemorySize, SM_BYTES);
        cudaFuncSetAttribute(gemm_mma_kernel<2>,
                             cudaFuncAttributeMaxDynamicSharedMemorySize, SM_BYTES);
    }

    const int gemm_blocks = (N + 127) / 128;
    const int agg_blocks  = (N + 7) / 8;
    const int e4b = (E + 1023) / 1024;  // 4 edges/thread kernels
    const int nb = (N + 1023) / 1024;   // scan blocks (<=128 for N<=131072)

    // ---- fork: CSR/degree build on side stream ----------------------------
    cudaEventRecord(ev_fork, 0);
    cudaStreamWaitEvent(s_side, ev_fork, 0);
    detect_kernel<<<1, 256, 0, s_side>>>(
        (const unsigned long long*)ei, E, (unsigned long long)N);
    zero_cnt_kernel<<<(N + 255) / 256, 256, 0, s_side>>>(N);
    cnt_accum_kernel<<<e4b, 256, 0, s_side>>>(ei, E, N);
    scan1_kernel<<<nb, 1024, 0, s_side>>>(N);
    scan2_kernel<<<1, 128, 0, s_side>>>(nb, N);
    scan3_kernel<<<nb, 1024, 0, s_side>>>(N);
    place_kernel<<<e4b, 256, 0, s_side>>>(ei, E, N);
    cudaEventRecord(ev_join, s_side);

    // ---- main stream: W prep + GEMM1 (independent of CSR) -----------------
    prep_w_kernel<<<64, 256>>>(W1, W2);
    gemm_mma_kernel<1><<<gemm_blocks, 256, SM_BYTES>>>(x, nullptr, N);

    // ---- join, then aggregation + layer 2 ----------------------------------
    cudaStreamWaitEvent(0, ev_join, 0);
    agg_kernel<false><<<agg_blocks, 256>>>(nullptr, nullptr, N);
    gemm_mma_kernel<2><<<gemm_blocks, 256, SM_BYTES>>>(nullptr, b1, N);
    agg_kernel<true><<<agg_blocks, 256>>>(b2, out, N);
}